// round 2
// baseline (speedup 1.0000x reference)
#include <cuda_runtime.h>
#include <cuda_bf16.h>
#include <math.h>

// Problem constants
#define BATCH 4
#define T_SEQ 2048
#define DMODEL 1024
#define NHEADS 16
#define DHEAD 64
#define WINDOW 256
#define NTOK (BATCH * T_SEQ)          // 8192
#define QKV_F (3 * DMODEL)            // 3072

// Scratch (device globals; allocation in kernel_launch is forbidden)
__device__ float g_qkv[(size_t)NTOK * QKV_F];   // [8192, 3072]  (q|k|v per token)
__device__ float g_attn[(size_t)NTOK * DMODEL]; // [8192, 1024]  attention output

// ---------------------------------------------------------------------------
// SGEMM: C[M,N] = A[M,K] * B[N,K]^T   (all row-major, M,N multiples of 128,
// K multiple of 16). 128x128x16 tile, 256 threads, 8x8 micro (split 4+4).
// Smem pad +4 keeps row stride (132 floats = 528B) a 16B multiple for LDS.128.
// ---------------------------------------------------------------------------
#define BM 128
#define BN 128
#define BK 16
#define BMP (BM + 4)
#define BNP (BN + 4)

__global__ __launch_bounds__(256, 2)
void sgemm_tn(const float* __restrict__ A, const float* __restrict__ B,
              float* __restrict__ C, int M, int N, int K) {
    __shared__ float As[BK][BMP];
    __shared__ float Bs[BK][BNP];

    const int bm = blockIdx.y * BM;
    const int bn = blockIdx.x * BN;
    const int tid = threadIdx.x;
    const int tx = tid & 15;   // 0..15
    const int ty = tid >> 4;   // 0..15

    float acc[8][8];
#pragma unroll
    for (int i = 0; i < 8; i++)
#pragma unroll
        for (int j = 0; j < 8; j++) acc[i][j] = 0.f;

    for (int k0 = 0; k0 < K; k0 += BK) {
#pragma unroll
        for (int l = 0; l < 2; l++) {
            int idx = tid + l * 256;        // 0..511
            int row = idx >> 2;             // 0..127
            int kq  = (idx & 3) * 4;        // 0,4,8,12
            float4 av = *(const float4*)&A[(size_t)(bm + row) * K + k0 + kq];
            As[kq + 0][row] = av.x; As[kq + 1][row] = av.y;
            As[kq + 2][row] = av.z; As[kq + 3][row] = av.w;
            float4 bv = *(const float4*)&B[(size_t)(bn + row) * K + k0 + kq];
            Bs[kq + 0][row] = bv.x; Bs[kq + 1][row] = bv.y;
            Bs[kq + 2][row] = bv.z; Bs[kq + 3][row] = bv.w;
        }
        __syncthreads();

#pragma unroll
        for (int k = 0; k < BK; k++) {
            float a[8], b[8];
            *(float4*)&a[0] = *(const float4*)&As[k][ty * 4];
            *(float4*)&a[4] = *(const float4*)&As[k][64 + ty * 4];
            *(float4*)&b[0] = *(const float4*)&Bs[k][tx * 4];
            *(float4*)&b[4] = *(const float4*)&Bs[k][64 + tx * 4];
#pragma unroll
            for (int i = 0; i < 8; i++)
#pragma unroll
                for (int j = 0; j < 8; j++) acc[i][j] += a[i] * b[j];
        }
        __syncthreads();
    }

#pragma unroll
    for (int i = 0; i < 8; i++) {
        int row = bm + (i < 4 ? ty * 4 + i : 64 + ty * 4 + (i - 4));
        float4 v0 = make_float4(acc[i][0], acc[i][1], acc[i][2], acc[i][3]);
        float4 v1 = make_float4(acc[i][4], acc[i][5], acc[i][6], acc[i][7]);
        *(float4*)&C[(size_t)row * N + bn + tx * 4]      = v0;
        *(float4*)&C[(size_t)row * N + bn + 64 + tx * 4] = v1;
    }
}

// ---------------------------------------------------------------------------
// RoPE applied in place to q,k parts of g_qkv.
// Each thread owns a (lane, lane+32) pair within one head of q or k.
// ---------------------------------------------------------------------------
__global__ void rope_kernel(float* __restrict__ qkv,
                            const float* __restrict__ cosb,
                            const float* __restrict__ sinb) {
    int idx = blockIdx.x * blockDim.x + threadIdx.x;   // 0 .. NTOK*1024-1
    int pair = idx & 1023;      // pair index within token across q+k
    int tok  = idx >> 10;       // 0..8191
    if (tok >= NTOK) return;
    int t = tok & (T_SEQ - 1);
    int sel  = pair >> 9;       // 0=q, 1=k
    int w    = pair & 511;
    int h    = w >> 5;          // head
    int lane = w & 31;          // 0..31
    int f = sel * DMODEL + h * DHEAD + lane;
    float* p = qkv + (size_t)tok * QKV_F;
    float x1 = p[f];
    float x2 = p[f + 32];
    float c1 = cosb[t * DHEAD + lane];
    float s1 = sinb[t * DHEAD + lane];
    float c2 = cosb[t * DHEAD + lane + 32];
    float s2 = sinb[t * DHEAD + lane + 32];
    p[f]      = x1 * c1 - x2 * s1;
    p[f + 32] = x2 * c2 + x1 * s2;
}

// ---------------------------------------------------------------------------
// Sliding-window attention. Block = (64 queries) x (head) x (batch).
// Online softmax over key chunks of 64. 256 threads:
//   qg = tid>>3 (32 groups, 2 queries each), kg = tid&7 (8 keys / 8 dims each)
// Kst/Vs use row stride 68 floats (272B, 16B multiple) since they are read
// with LDS.128; Qs/Ps are scalar-accessed and keep stride 65.
// SMEM bytes: 64*(65 + 68 + 68 + 65)*4 = 68096
// ---------------------------------------------------------------------------
#define ATTN_SMEM (64 * (65 + 68 + 68 + 65) * 4)

__global__ __launch_bounds__(256)
void attn_kernel(const float* __restrict__ qkv, float* __restrict__ out) {
    extern __shared__ float sm[];
    float (*Qs)[65]  = (float(*)[65])(sm);
    float (*Kst)[68] = (float(*)[68])(sm + 64 * 65);                 // Kst[d][k]
    float (*Vs)[68]  = (float(*)[68])(sm + 64 * 65 + 64 * 68);      // Vs[k][d]
    float (*Ps)[65]  = (float(*)[65])(sm + 64 * 65 + 2 * 64 * 68);  // Ps[q][k]

    const int qb = blockIdx.x;
    const int h  = blockIdx.y;
    const int b  = blockIdx.z;
    const int q0 = qb * 64;
    const int tid = threadIdx.x;
    const int qg = tid >> 3;   // 0..31
    const int kg = tid & 7;    // 0..7

    const float scale = 0.125f;  // 1/sqrt(64)

    // Load Q tile (scaled)
    for (int l = tid; l < 64 * 16; l += 256) {
        int r = l >> 4, c = (l & 15) * 4;
        float4 v = *(const float4*)&qkv[((size_t)(b * T_SEQ + q0 + r)) * QKV_F + h * DHEAD + c];
        Qs[r][c]     = v.x * scale; Qs[r][c + 1] = v.y * scale;
        Qs[r][c + 2] = v.z * scale; Qs[r][c + 3] = v.w * scale;
    }

    float m[2]    = {-1e30f, -1e30f};
    float lsum[2] = {0.f, 0.f};
    float acc[2][8];
#pragma unroll
    for (int i = 0; i < 2; i++)
#pragma unroll
        for (int j = 0; j < 8; j++) acc[i][j] = 0.f;

    int lo = max(0, q0 - (WINDOW - 1)) >> 6;

    for (int kc = lo; kc <= qb; kc++) {
        const int k0 = kc * 64;
        __syncthreads();
        // Load K (transposed into Kst) and V chunk
        for (int l = tid; l < 64 * 16; l += 256) {
            int r = l >> 4, c = (l & 15) * 4;
            const float* base = &qkv[((size_t)(b * T_SEQ + k0 + r)) * QKV_F + h * DHEAD + c];
            float4 kv = *(const float4*)(base + DMODEL);
            Kst[c + 0][r] = kv.x; Kst[c + 1][r] = kv.y;
            Kst[c + 2][r] = kv.z; Kst[c + 3][r] = kv.w;
            float4 vv = *(const float4*)(base + 2 * DMODEL);
            Vs[r][c] = vv.x; Vs[r][c + 1] = vv.y; Vs[r][c + 2] = vv.z; Vs[r][c + 3] = vv.w;
        }
        __syncthreads();

        // Scores: s[i][j] = Q[qg*2+i] . K[kg*8+j]
        float s[2][8];
#pragma unroll
        for (int i = 0; i < 2; i++)
#pragma unroll
            for (int j = 0; j < 8; j++) s[i][j] = 0.f;

#pragma unroll 8
        for (int d = 0; d < 64; d++) {
            float kr[8];
            *(float4*)&kr[0] = *(const float4*)&Kst[d][kg * 8];
            *(float4*)&kr[4] = *(const float4*)&Kst[d][kg * 8 + 4];
#pragma unroll
            for (int i = 0; i < 2; i++) {
                float qv = Qs[qg * 2 + i][d];
#pragma unroll
                for (int j = 0; j < 8; j++) s[i][j] += qv * kr[j];
            }
        }

        // Mask + online softmax update (reduce over 8 kg lanes)
#pragma unroll
        for (int i = 0; i < 2; i++) {
            int i_abs = q0 + qg * 2 + i;
            float cmax = -1e30f;
#pragma unroll
            for (int j = 0; j < 8; j++) {
                int j_abs = k0 + kg * 8 + j;
                bool ok = (j_abs <= i_abs) && (j_abs >= i_abs - (WINDOW - 1));
                if (!ok) s[i][j] = -1e30f;
                cmax = fmaxf(cmax, s[i][j]);
            }
            cmax = fmaxf(cmax, __shfl_xor_sync(0xffffffffu, cmax, 1));
            cmax = fmaxf(cmax, __shfl_xor_sync(0xffffffffu, cmax, 2));
            cmax = fmaxf(cmax, __shfl_xor_sync(0xffffffffu, cmax, 4));
            float mnew = fmaxf(m[i], cmax);
            float corr = __expf(m[i] - mnew);   // if both -1e30: exp(0)=1, acc/lsum are 0 -> OK
            float ps = 0.f;
#pragma unroll
            for (int j = 0; j < 8; j++) {
                float p = (s[i][j] > -5e29f) ? __expf(s[i][j] - mnew) : 0.f;
                s[i][j] = p;
                ps += p;
            }
            ps += __shfl_xor_sync(0xffffffffu, ps, 1);
            ps += __shfl_xor_sync(0xffffffffu, ps, 2);
            ps += __shfl_xor_sync(0xffffffffu, ps, 4);
            lsum[i] = lsum[i] * corr + ps;
            m[i] = mnew;
#pragma unroll
            for (int j = 0; j < 8; j++) {
                acc[i][j] *= corr;
                Ps[qg * 2 + i][kg * 8 + j] = s[i][j];
            }
        }
        __syncwarp();   // Ps producers & consumers for a given q live in the same warp

        // PV: acc[i][dd] += sum_k Ps[q][k] * V[k][kg*8+dd]
#pragma unroll 8
        for (int k = 0; k < 64; k++) {
            float vr[8];
            *(float4*)&vr[0] = *(const float4*)&Vs[k][kg * 8];
            *(float4*)&vr[4] = *(const float4*)&Vs[k][kg * 8 + 4];
#pragma unroll
            for (int i = 0; i < 2; i++) {
                float p = Ps[qg * 2 + i][k];
#pragma unroll
                for (int j = 0; j < 8; j++) acc[i][j] += p * vr[j];
            }
        }
    }

    // Write normalized output: [tok, h*64 + d]
#pragma unroll
    for (int i = 0; i < 2; i++) {
        float inv = 1.f / lsum[i];
        float4 v0 = make_float4(acc[i][0] * inv, acc[i][1] * inv, acc[i][2] * inv, acc[i][3] * inv);
        float4 v1 = make_float4(acc[i][4] * inv, acc[i][5] * inv, acc[i][6] * inv, acc[i][7] * inv);
        size_t base = ((size_t)(b * T_SEQ + q0 + qg * 2 + i)) * DMODEL + h * DHEAD + kg * 8;
        *(float4*)&out[base]     = v0;
        *(float4*)&out[base + 4] = v1;
    }
}

// ---------------------------------------------------------------------------
// Launch
// ---------------------------------------------------------------------------
extern "C" void kernel_launch(void* const* d_in, const int* in_sizes, int n_in,
                              void* d_out, int out_size) {
    const float* x     = (const float*)d_in[0];  // [4,2048,1024]
    const float* cosb  = (const float*)d_in[1];  // [1,2048,1,64]
    const float* sinb  = (const float*)d_in[2];  // [1,2048,1,64]
    const float* qkv_w = (const float*)d_in[3];  // [3072,1024]
    const float* out_w = (const float*)d_in[4];  // [1024,1024]
    float* out = (float*)d_out;

    float* qkv = nullptr;
    float* attn = nullptr;
    cudaGetSymbolAddress((void**)&qkv, g_qkv);
    cudaGetSymbolAddress((void**)&attn, g_attn);
    cudaFuncSetAttribute(attn_kernel, cudaFuncAttributeMaxDynamicSharedMemorySize, ATTN_SMEM);

    // 1) QKV projection: [8192,3072] = x[8192,1024] @ qkv_w^T
    {
        dim3 grid(QKV_F / BN, NTOK / BM);
        sgemm_tn<<<grid, 256>>>(x, qkv_w, qkv, NTOK, QKV_F, DMODEL);
    }
    // 2) RoPE on q,k
    {
        int total = NTOK * 1024;
        rope_kernel<<<total / 256, 256>>>(qkv, cosb, sinb);
    }
    // 3) Sliding-window attention
    {
        dim3 grid(T_SEQ / 64, NHEADS, BATCH);
        attn_kernel<<<grid, 256, ATTN_SMEM>>>(qkv, attn);
    }
    // 4) Output projection: [8192,1024] = attn @ out_w^T
    {
        dim3 grid(DMODEL / BN, NTOK / BM);
        sgemm_tn<<<grid, 256>>>(attn, out_w, out, NTOK, DMODEL, DMODEL);
    }
}

// round 4
// speedup vs baseline: 1.5060x; 1.5060x over previous
#include <cuda_runtime.h>
#include <cuda_bf16.h>
#include <math.h>
#include <stdint.h>

// Problem constants
#define BATCH 4
#define T_SEQ 2048
#define DMODEL 1024
#define NHEADS 16
#define DHEAD 64
#define WINDOW 256
#define NTOK (BATCH * T_SEQ)          // 8192
#define QKV_F (3 * DMODEL)            // 3072
#define KDIM 1024

// Scratch (device globals; allocation in kernel_launch is forbidden)
__device__ float g_qkv[(size_t)NTOK * QKV_F];
__device__ __nv_bfloat16 g_xhi[(size_t)NTOK * DMODEL];
__device__ __nv_bfloat16 g_xlo[(size_t)NTOK * DMODEL];
__device__ __nv_bfloat16 g_whi[(size_t)QKV_F * DMODEL];
__device__ __nv_bfloat16 g_wlo[(size_t)QKV_F * DMODEL];
__device__ __nv_bfloat16 g_ohi[(size_t)DMODEL * DMODEL];
__device__ __nv_bfloat16 g_olo[(size_t)DMODEL * DMODEL];
__device__ __nv_bfloat16 g_ahi[(size_t)NTOK * DMODEL];
__device__ __nv_bfloat16 g_alo[(size_t)NTOK * DMODEL];

// ---------------------------------------------------------------------------
// Helpers
// ---------------------------------------------------------------------------
__device__ __forceinline__ void split1(float x, __nv_bfloat16& h, __nv_bfloat16& l) {
    h = __float2bfloat16(x);
    l = __float2bfloat16(x - __bfloat162float(h));
}

__global__ void split_kernel(const float* __restrict__ in,
                             __nv_bfloat16* __restrict__ hi,
                             __nv_bfloat16* __restrict__ lo, int n4) {
    int i = blockIdx.x * 256 + threadIdx.x;
    if (i >= n4) return;
    float4 v = ((const float4*)in)[i];
    __align__(8) __nv_bfloat16 h4[4], l4[4];
    split1(v.x, h4[0], l4[0]); split1(v.y, h4[1], l4[1]);
    split1(v.z, h4[2], l4[2]); split1(v.w, h4[3], l4[3]);
    ((uint2*)hi)[i] = *(uint2*)h4;
    ((uint2*)lo)[i] = *(uint2*)l4;
}

__device__ __forceinline__ void cp_async16(uint32_t dst, const void* src) {
    asm volatile("cp.async.cg.shared.global [%0], [%1], 16;" :: "r"(dst), "l"(src) : "memory");
}
__device__ __forceinline__ void cp_commit() {
    asm volatile("cp.async.commit_group;" ::: "memory");
}
template <int N>
__device__ __forceinline__ void cp_wait() {
    asm volatile("cp.async.wait_group %0;" :: "n"(N) : "memory");
}

#define MMA_BF16(d, a, b)                                                       \
    asm volatile("mma.sync.aligned.m16n8k16.row.col.f32.bf16.bf16.f32 "         \
                 "{%0,%1,%2,%3}, {%4,%5,%6,%7}, {%8,%9}, {%0,%1,%2,%3};"        \
                 : "+f"((d)[0]), "+f"((d)[1]), "+f"((d)[2]), "+f"((d)[3])       \
                 : "r"((a)[0]), "r"((a)[1]), "r"((a)[2]), "r"((a)[3]),          \
                   "r"((b)[0]), "r"((b)[1]))

// ---------------------------------------------------------------------------
// bf16x3 HMMA GEMM: C[M,N] = (Ah+Al)[M,K] * ((Bh+Bl)[N,K])^T, fp32 accum.
// Tile 128x128, BK=32, 8 warps (2x4), warp tile 64x32, double-buffer cp.async.
// SMEM per stage: 4 parts (Ah,Al,Bh,Bl) x 128 rows x 40 bf16 (80B stride).
// ---------------------------------------------------------------------------
#define ROWB 80                     // smem row stride bytes (40 bf16)
#define PART (128 * ROWB)           // 10240 bytes per part
#define STAGE (4 * PART)            // 40960 bytes
#define GEMM_SMEM (2 * STAGE)       // 81920

__global__ __launch_bounds__(256)
void gemm_hmma_x3(const __nv_bfloat16* __restrict__ Ah, const __nv_bfloat16* __restrict__ Al,
                  const __nv_bfloat16* __restrict__ Bh, const __nv_bfloat16* __restrict__ Bl,
                  float* __restrict__ C, int N) {
    extern __shared__ __align__(16) char dynsm[];
    const int tid  = threadIdx.x;
    const int warp = tid >> 5, lane = tid & 31;
    const int g = lane >> 2, tig = lane & 3;
    const int warp_m = warp >> 2;          // 0..1
    const int warp_n = warp & 3;           // 0..3
    const int m0 = blockIdx.y * 128;
    const int n0 = blockIdx.x * 128;

    uint32_t smbase;
    asm("{ .reg .u64 t; cvta.to.shared.u64 t, %1; cvt.u32.u64 %0, t; }"
        : "=r"(smbase) : "l"(dynsm));

    const __nv_bfloat16* gsrc[4] = {Ah + (size_t)m0 * KDIM, Al + (size_t)m0 * KDIM,
                                    Bh + (size_t)n0 * KDIM, Bl + (size_t)n0 * KDIM};

    auto load_stage = [&](int c) {
        const int st = c & 1;
        const int k0 = c * 32;
        const uint32_t sb = smbase + st * STAGE;
#pragma unroll
        for (int p = 0; p < 4; ++p) {
#pragma unroll
            for (int l = 0; l < 2; ++l) {
                int idx = tid + l * 256;
                int r = idx >> 2, c8 = idx & 3;
                cp_async16(sb + p * PART + r * ROWB + c8 * 16,
                           gsrc[p] + (size_t)r * KDIM + k0 + c8 * 8);
            }
        }
    };

    float acc[4][4][4];
#pragma unroll
    for (int i = 0; i < 4; i++)
#pragma unroll
        for (int j = 0; j < 4; j++)
#pragma unroll
            for (int v = 0; v < 4; v++) acc[i][j][v] = 0.f;

    load_stage(0);
    cp_commit();

    const int NC = KDIM / 32;   // 32 chunks
    for (int c = 0; c < NC; ++c) {
        if (c + 1 < NC) { load_stage(c + 1); cp_commit(); cp_wait<1>(); }
        else           { cp_wait<0>(); }
        __syncthreads();

        const uint32_t sb = smbase + (c & 1) * STAGE;
        const uint32_t sAh = sb,            sAl = sb + PART;
        const uint32_t sBh = sb + 2 * PART, sBl = sb + 3 * PART;

#pragma unroll
        for (int s = 0; s < 2; ++s) {
            const int ksb = s * 32 + tig * 4;   // byte offset of k-frag pair
            uint32_t Afh[4][4], Afl[4][4], Bfh[4][2], Bfl[4][2];
#pragma unroll
            for (int i = 0; i < 4; ++i) {
                uint32_t ro = (uint32_t)((warp_m * 64 + i * 16 + g) * ROWB + ksb);
                Afh[i][0] = *(const uint32_t*)(dynsm + (sAh - smbase) + ro);
                Afh[i][1] = *(const uint32_t*)(dynsm + (sAh - smbase) + ro + 8 * ROWB);
                Afh[i][2] = *(const uint32_t*)(dynsm + (sAh - smbase) + ro + 16);
                Afh[i][3] = *(const uint32_t*)(dynsm + (sAh - smbase) + ro + 8 * ROWB + 16);
                Afl[i][0] = *(const uint32_t*)(dynsm + (sAl - smbase) + ro);
                Afl[i][1] = *(const uint32_t*)(dynsm + (sAl - smbase) + ro + 8 * ROWB);
                Afl[i][2] = *(const uint32_t*)(dynsm + (sAl - smbase) + ro + 16);
                Afl[i][3] = *(const uint32_t*)(dynsm + (sAl - smbase) + ro + 8 * ROWB + 16);
            }
#pragma unroll
            for (int j = 0; j < 4; ++j) {
                uint32_t ro = (uint32_t)((warp_n * 32 + j * 8 + g) * ROWB + ksb);
                Bfh[j][0] = *(const uint32_t*)(dynsm + (sBh - smbase) + ro);
                Bfh[j][1] = *(const uint32_t*)(dynsm + (sBh - smbase) + ro + 16);
                Bfl[j][0] = *(const uint32_t*)(dynsm + (sBl - smbase) + ro);
                Bfl[j][1] = *(const uint32_t*)(dynsm + (sBl - smbase) + ro + 16);
            }
#pragma unroll
            for (int i = 0; i < 4; ++i)
#pragma unroll
                for (int j = 0; j < 4; ++j) {
                    MMA_BF16(acc[i][j], Afh[i], Bfh[j]);
                    MMA_BF16(acc[i][j], Afh[i], Bfl[j]);
                    MMA_BF16(acc[i][j], Afl[i], Bfh[j]);
                }
        }
        __syncthreads();
    }

    // Epilogue: fp32 direct store (float2 per fragment row)
#pragma unroll
    for (int i = 0; i < 4; ++i) {
        int row = m0 + warp_m * 64 + i * 16 + g;
#pragma unroll
        for (int j = 0; j < 4; ++j) {
            int col = n0 + warp_n * 32 + j * 8 + tig * 2;
            *(float2*)&C[(size_t)row * N + col] =
                make_float2(acc[i][j][0], acc[i][j][1]);
            *(float2*)&C[(size_t)(row + 8) * N + col] =
                make_float2(acc[i][j][2], acc[i][j][3]);
        }
    }
}

// ---------------------------------------------------------------------------
// RoPE applied in place to q,k parts of g_qkv.
// ---------------------------------------------------------------------------
__global__ void rope_kernel(float* __restrict__ qkv,
                            const float* __restrict__ cosb,
                            const float* __restrict__ sinb) {
    int idx = blockIdx.x * blockDim.x + threadIdx.x;
    int pair = idx & 1023;
    int tok  = idx >> 10;
    if (tok >= NTOK) return;
    int t = tok & (T_SEQ - 1);
    int sel  = pair >> 9;
    int w    = pair & 511;
    int h    = w >> 5;
    int lane = w & 31;
    int f = sel * DMODEL + h * DHEAD + lane;
    float* p = qkv + (size_t)tok * QKV_F;
    float x1 = p[f];
    float x2 = p[f + 32];
    float c1 = cosb[t * DHEAD + lane];
    float s1 = sinb[t * DHEAD + lane];
    float c2 = cosb[t * DHEAD + lane + 32];
    float s2 = sinb[t * DHEAD + lane + 32];
    p[f]      = x1 * c1 - x2 * s1;
    p[f + 32] = x2 * c2 + x1 * s2;
}

// ---------------------------------------------------------------------------
// Sliding-window attention (fp32), epilogue emits bf16 hi/lo for GEMM2.
// ---------------------------------------------------------------------------
#define ATTN_SMEM (64 * (65 + 68 + 68 + 65) * 4)

__global__ __launch_bounds__(256)
void attn_kernel(const float* __restrict__ qkv,
                 __nv_bfloat16* __restrict__ ahi,
                 __nv_bfloat16* __restrict__ alo) {
    extern __shared__ float sm[];
    float (*Qs)[65]  = (float(*)[65])(sm);
    float (*Kst)[68] = (float(*)[68])(sm + 64 * 65);
    float (*Vs)[68]  = (float(*)[68])(sm + 64 * 65 + 64 * 68);
    float (*Ps)[65]  = (float(*)[65])(sm + 64 * 65 + 2 * 64 * 68);

    const int qb = blockIdx.x;
    const int h  = blockIdx.y;
    const int b  = blockIdx.z;
    const int q0 = qb * 64;
    const int tid = threadIdx.x;
    const int qg = tid >> 3;
    const int kg = tid & 7;

    const float scale = 0.125f;

    for (int l = tid; l < 64 * 16; l += 256) {
        int r = l >> 4, c = (l & 15) * 4;
        float4 v = *(const float4*)&qkv[((size_t)(b * T_SEQ + q0 + r)) * QKV_F + h * DHEAD + c];
        Qs[r][c]     = v.x * scale; Qs[r][c + 1] = v.y * scale;
        Qs[r][c + 2] = v.z * scale; Qs[r][c + 3] = v.w * scale;
    }

    float m[2]    = {-1e30f, -1e30f};
    float lsum[2] = {0.f, 0.f};
    float acc[2][8];
#pragma unroll
    for (int i = 0; i < 2; i++)
#pragma unroll
        for (int j = 0; j < 8; j++) acc[i][j] = 0.f;

    int lo = max(0, q0 - (WINDOW - 1)) >> 6;

    for (int kc = lo; kc <= qb; kc++) {
        const int k0 = kc * 64;
        __syncthreads();
        for (int l = tid; l < 64 * 16; l += 256) {
            int r = l >> 4, c = (l & 15) * 4;
            const float* bp = &qkv[((size_t)(b * T_SEQ + k0 + r)) * QKV_F + h * DHEAD + c];
            float4 kv = *(const float4*)(bp + DMODEL);
            Kst[c + 0][r] = kv.x; Kst[c + 1][r] = kv.y;
            Kst[c + 2][r] = kv.z; Kst[c + 3][r] = kv.w;
            float4 vv = *(const float4*)(bp + 2 * DMODEL);
            Vs[r][c] = vv.x; Vs[r][c + 1] = vv.y; Vs[r][c + 2] = vv.z; Vs[r][c + 3] = vv.w;
        }
        __syncthreads();

        float s[2][8];
#pragma unroll
        for (int i = 0; i < 2; i++)
#pragma unroll
            for (int j = 0; j < 8; j++) s[i][j] = 0.f;

#pragma unroll 8
        for (int d = 0; d < 64; d++) {
            float kr[8];
            *(float4*)&kr[0] = *(const float4*)&Kst[d][kg * 8];
            *(float4*)&kr[4] = *(const float4*)&Kst[d][kg * 8 + 4];
#pragma unroll
            for (int i = 0; i < 2; i++) {
                float qv = Qs[qg * 2 + i][d];
#pragma unroll
                for (int j = 0; j < 8; j++) s[i][j] += qv * kr[j];
            }
        }

#pragma unroll
        for (int i = 0; i < 2; i++) {
            int i_abs = q0 + qg * 2 + i;
            float cmax = -1e30f;
#pragma unroll
            for (int j = 0; j < 8; j++) {
                int j_abs = k0 + kg * 8 + j;
                bool ok = (j_abs <= i_abs) && (j_abs >= i_abs - (WINDOW - 1));
                if (!ok) s[i][j] = -1e30f;
                cmax = fmaxf(cmax, s[i][j]);
            }
            cmax = fmaxf(cmax, __shfl_xor_sync(0xffffffffu, cmax, 1));
            cmax = fmaxf(cmax, __shfl_xor_sync(0xffffffffu, cmax, 2));
            cmax = fmaxf(cmax, __shfl_xor_sync(0xffffffffu, cmax, 4));
            float mnew = fmaxf(m[i], cmax);
            float corr = __expf(m[i] - mnew);
            float ps = 0.f;
#pragma unroll
            for (int j = 0; j < 8; j++) {
                float p = (s[i][j] > -5e29f) ? __expf(s[i][j] - mnew) : 0.f;
                s[i][j] = p;
                ps += p;
            }
            ps += __shfl_xor_sync(0xffffffffu, ps, 1);
            ps += __shfl_xor_sync(0xffffffffu, ps, 2);
            ps += __shfl_xor_sync(0xffffffffu, ps, 4);
            lsum[i] = lsum[i] * corr + ps;
            m[i] = mnew;
#pragma unroll
            for (int j = 0; j < 8; j++) {
                acc[i][j] *= corr;
                Ps[qg * 2 + i][kg * 8 + j] = s[i][j];
            }
        }
        __syncwarp();

#pragma unroll 8
        for (int k = 0; k < 64; k++) {
            float vr[8];
            *(float4*)&vr[0] = *(const float4*)&Vs[k][kg * 8];
            *(float4*)&vr[4] = *(const float4*)&Vs[k][kg * 8 + 4];
#pragma unroll
            for (int i = 0; i < 2; i++) {
                float p = Ps[qg * 2 + i][k];
#pragma unroll
                for (int j = 0; j < 8; j++) acc[i][j] += p * vr[j];
            }
        }
    }

#pragma unroll
    for (int i = 0; i < 2; i++) {
        float inv = 1.f / lsum[i];
        __align__(16) __nv_bfloat16 hv[8], lv[8];
#pragma unroll
        for (int j = 0; j < 8; j++) {
            float v = acc[i][j] * inv;
            split1(v, hv[j], lv[j]);
        }
        size_t bidx = ((size_t)(b * T_SEQ + q0 + qg * 2 + i)) * DMODEL + h * DHEAD + kg * 8;
        *(uint4*)&ahi[bidx] = *(uint4*)hv;
        *(uint4*)&alo[bidx] = *(uint4*)lv;
    }
}

// ---------------------------------------------------------------------------
// Launch
// ---------------------------------------------------------------------------
extern "C" void kernel_launch(void* const* d_in, const int* in_sizes, int n_in,
                              void* d_out, int out_size) {
    const float* x     = (const float*)d_in[0];
    const float* cosb  = (const float*)d_in[1];
    const float* sinb  = (const float*)d_in[2];
    const float* qkv_w = (const float*)d_in[3];
    const float* out_w = (const float*)d_in[4];
    float* out = (float*)d_out;

    float *qkv = nullptr;
    __nv_bfloat16 *xhi, *xlo, *whi, *wlo, *ohi, *olo, *ahi, *alo;
    cudaGetSymbolAddress((void**)&qkv, g_qkv);
    cudaGetSymbolAddress((void**)&xhi, g_xhi);
    cudaGetSymbolAddress((void**)&xlo, g_xlo);
    cudaGetSymbolAddress((void**)&whi, g_whi);
    cudaGetSymbolAddress((void**)&wlo, g_wlo);
    cudaGetSymbolAddress((void**)&ohi, g_ohi);
    cudaGetSymbolAddress((void**)&olo, g_olo);
    cudaGetSymbolAddress((void**)&ahi, g_ahi);
    cudaGetSymbolAddress((void**)&alo, g_alo);

    cudaFuncSetAttribute(gemm_hmma_x3, cudaFuncAttributeMaxDynamicSharedMemorySize, GEMM_SMEM);
    cudaFuncSetAttribute(attn_kernel, cudaFuncAttributeMaxDynamicSharedMemorySize, ATTN_SMEM);

    // 0) Split inputs/weights into bf16 hi/lo
    split_kernel<<<(NTOK * DMODEL / 4 + 255) / 256, 256>>>(x, xhi, xlo, NTOK * DMODEL / 4);
    split_kernel<<<(QKV_F * DMODEL / 4 + 255) / 256, 256>>>(qkv_w, whi, wlo, QKV_F * DMODEL / 4);
    split_kernel<<<(DMODEL * DMODEL / 4 + 255) / 256, 256>>>(out_w, ohi, olo, DMODEL * DMODEL / 4);

    // 1) QKV projection (HMMA bf16x3): [8192,3072] = x @ qkv_w^T
    {
        dim3 grid(QKV_F / 128, NTOK / 128);
        gemm_hmma_x3<<<grid, 256, GEMM_SMEM>>>(xhi, xlo, whi, wlo, qkv, QKV_F);
    }
    // 2) RoPE on q,k (fp32, in place)
    rope_kernel<<<(NTOK * 1024) / 256, 256>>>(qkv, cosb, sinb);
    // 3) Sliding-window attention (fp32 in, bf16 hi/lo out)
    {
        dim3 grid(T_SEQ / 64, NHEADS, BATCH);
        attn_kernel<<<grid, 256, ATTN_SMEM>>>(qkv, ahi, alo);
    }
    // 4) Output projection (HMMA bf16x3): [8192,1024] = attn @ out_w^T
    {
        dim3 grid(DMODEL / 128, NTOK / 128);
        gemm_hmma_x3<<<grid, 256, GEMM_SMEM>>>(ahi, alo, ohi, olo, out, DMODEL);
    }
}

// round 5
// speedup vs baseline: 1.5722x; 1.0439x over previous
#include <cuda_runtime.h>
#include <cuda_bf16.h>
#include <math.h>
#include <stdint.h>

// Problem constants
#define BATCH 4
#define T_SEQ 2048
#define DMODEL 1024
#define NHEADS 16
#define DHEAD 64
#define WINDOW 256
#define NTOK (BATCH * T_SEQ)          // 8192
#define QKV_F (3 * DMODEL)            // 3072
#define KDIM 1024

// Scratch (device globals; allocation in kernel_launch is forbidden)
__device__ float g_qkv[(size_t)NTOK * QKV_F];
__device__ __nv_bfloat16 g_xhi[(size_t)NTOK * DMODEL];
__device__ __nv_bfloat16 g_xlo[(size_t)NTOK * DMODEL];
__device__ __nv_bfloat16 g_whi[(size_t)QKV_F * DMODEL];
__device__ __nv_bfloat16 g_wlo[(size_t)QKV_F * DMODEL];
__device__ __nv_bfloat16 g_ohi[(size_t)DMODEL * DMODEL];
__device__ __nv_bfloat16 g_olo[(size_t)DMODEL * DMODEL];
__device__ __nv_bfloat16 g_ahi[(size_t)NTOK * DMODEL];
__device__ __nv_bfloat16 g_alo[(size_t)NTOK * DMODEL];

// ---------------------------------------------------------------------------
// Helpers
// ---------------------------------------------------------------------------
__device__ __forceinline__ void split1(float x, __nv_bfloat16& h, __nv_bfloat16& l) {
    h = __float2bfloat16(x);
    l = __float2bfloat16(x - __bfloat162float(h));
}

__global__ void split_kernel(const float* __restrict__ in,
                             __nv_bfloat16* __restrict__ hi,
                             __nv_bfloat16* __restrict__ lo, int n4) {
    int i = blockIdx.x * 256 + threadIdx.x;
    if (i >= n4) return;
    float4 v = ((const float4*)in)[i];
    __align__(8) __nv_bfloat16 h4[4], l4[4];
    split1(v.x, h4[0], l4[0]); split1(v.y, h4[1], l4[1]);
    split1(v.z, h4[2], l4[2]); split1(v.w, h4[3], l4[3]);
    ((uint2*)hi)[i] = *(uint2*)h4;
    ((uint2*)lo)[i] = *(uint2*)l4;
}

__device__ __forceinline__ void cp_async16(uint32_t dst, const void* src) {
    asm volatile("cp.async.cg.shared.global [%0], [%1], 16;" :: "r"(dst), "l"(src) : "memory");
}
__device__ __forceinline__ void cp_commit() {
    asm volatile("cp.async.commit_group;" ::: "memory");
}
template <int N>
__device__ __forceinline__ void cp_wait() {
    asm volatile("cp.async.wait_group %0;" :: "n"(N) : "memory");
}

#define MMA_BF16(d, a, b)                                                       \
    asm volatile("mma.sync.aligned.m16n8k16.row.col.f32.bf16.bf16.f32 "         \
                 "{%0,%1,%2,%3}, {%4,%5,%6,%7}, {%8,%9}, {%0,%1,%2,%3};"        \
                 : "+f"((d)[0]), "+f"((d)[1]), "+f"((d)[2]), "+f"((d)[3])       \
                 : "r"((a)[0]), "r"((a)[1]), "r"((a)[2]), "r"((a)[3]),          \
                   "r"((b)[0]), "r"((b)[1]))

// ---------------------------------------------------------------------------
// bf16x3 HMMA GEMM: C[M,N] = (Ah+Al)[M,K] * ((Bh+Bl)[N,K])^T, fp32 accum.
// Tile 128x256, BK=32, 8 warps (2x4), warp tile 64x64, 3-stage cp.async.
// SMEM rows: 40 bf16 stride (80B) -> conflict-free for (g,tig) frag loads.
// ---------------------------------------------------------------------------
#define ROWB 80
#define APART (128 * ROWB)                 // 10240 B
#define BPART (256 * ROWB)                 // 20480 B
#define STAGE (2 * APART + 2 * BPART)      // 61440 B
#define NSTAGE 3
#define GEMM_SMEM (NSTAGE * STAGE)         // 184320 B

__global__ __launch_bounds__(256, 1)
void gemm_hmma_x3(const __nv_bfloat16* __restrict__ Ah, const __nv_bfloat16* __restrict__ Al,
                  const __nv_bfloat16* __restrict__ Bh, const __nv_bfloat16* __restrict__ Bl,
                  float* __restrict__ C, int N) {
    extern __shared__ __align__(16) char dynsm[];
    const int tid  = threadIdx.x;
    const int warp = tid >> 5, lane = tid & 31;
    const int g = lane >> 2, tig = lane & 3;
    const int warp_m = warp >> 2;          // 0..1
    const int warp_n = warp & 3;           // 0..3
    const int m0 = blockIdx.y * 128;
    const int n0 = blockIdx.x * 256;

    uint32_t smbase;
    asm("{ .reg .u64 t; cvta.to.shared.u64 t, %1; cvt.u32.u64 %0, t; }"
        : "=r"(smbase) : "l"(dynsm));

    const __nv_bfloat16* Ah_ = Ah + (size_t)m0 * KDIM;
    const __nv_bfloat16* Al_ = Al + (size_t)m0 * KDIM;
    const __nv_bfloat16* Bh_ = Bh + (size_t)n0 * KDIM;
    const __nv_bfloat16* Bl_ = Bl + (size_t)n0 * KDIM;

    auto load_stage = [&](int c) {
        const uint32_t sb = smbase + (c % NSTAGE) * STAGE;
        const int k0 = c * 32;
#pragma unroll
        for (int l = 0; l < 2; ++l) {               // A parts: 512 chunks
            int idx = tid + l * 256;
            int r = idx >> 2, c8 = idx & 3;
            size_t go = (size_t)r * KDIM + k0 + c8 * 8;
            uint32_t so = (uint32_t)(r * ROWB + c8 * 16);
            cp_async16(sb + so,         Ah_ + go);
            cp_async16(sb + APART + so, Al_ + go);
        }
#pragma unroll
        for (int l = 0; l < 4; ++l) {               // B parts: 1024 chunks
            int idx = tid + l * 256;
            int r = idx >> 2, c8 = idx & 3;
            size_t go = (size_t)r * KDIM + k0 + c8 * 8;
            uint32_t so = (uint32_t)(r * ROWB + c8 * 16);
            cp_async16(sb + 2 * APART + so,         Bh_ + go);
            cp_async16(sb + 2 * APART + BPART + so, Bl_ + go);
        }
    };

    float acc[4][8][4];
#pragma unroll
    for (int i = 0; i < 4; i++)
#pragma unroll
        for (int j = 0; j < 8; j++)
#pragma unroll
            for (int v = 0; v < 4; v++) acc[i][j][v] = 0.f;

    load_stage(0); cp_commit();
    load_stage(1); cp_commit();

    const int NC = KDIM / 32;   // 32 chunks
    for (int c = 0; c < NC; ++c) {
        cp_wait<1>();
        __syncthreads();
        if (c + 2 < NC) load_stage(c + 2);
        cp_commit();

        const uint32_t sb  = smbase + (c % NSTAGE) * STAGE;
        const uint32_t sAh = sb,               sAl = sb + APART;
        const uint32_t sBh = sb + 2 * APART,   sBl = sb + 2 * APART + BPART;

#pragma unroll
        for (int s = 0; s < 2; ++s) {
            const int ksb = s * 32 + tig * 4;
            uint32_t Afh[4][4], Afl[4][4], Bfh[8][2], Bfl[8][2];
#pragma unroll
            for (int i = 0; i < 4; ++i) {
                uint32_t ro = (uint32_t)((warp_m * 64 + i * 16 + g) * ROWB + ksb);
                asm volatile("ld.shared.b32 %0, [%1];" : "=r"(Afh[i][0]) : "r"(sAh + ro));
                asm volatile("ld.shared.b32 %0, [%1];" : "=r"(Afh[i][1]) : "r"(sAh + ro + 8 * ROWB));
                asm volatile("ld.shared.b32 %0, [%1];" : "=r"(Afh[i][2]) : "r"(sAh + ro + 16));
                asm volatile("ld.shared.b32 %0, [%1];" : "=r"(Afh[i][3]) : "r"(sAh + ro + 8 * ROWB + 16));
                asm volatile("ld.shared.b32 %0, [%1];" : "=r"(Afl[i][0]) : "r"(sAl + ro));
                asm volatile("ld.shared.b32 %0, [%1];" : "=r"(Afl[i][1]) : "r"(sAl + ro + 8 * ROWB));
                asm volatile("ld.shared.b32 %0, [%1];" : "=r"(Afl[i][2]) : "r"(sAl + ro + 16));
                asm volatile("ld.shared.b32 %0, [%1];" : "=r"(Afl[i][3]) : "r"(sAl + ro + 8 * ROWB + 16));
            }
#pragma unroll
            for (int j = 0; j < 8; ++j) {
                uint32_t ro = (uint32_t)((warp_n * 64 + j * 8 + g) * ROWB + ksb);
                asm volatile("ld.shared.b32 %0, [%1];" : "=r"(Bfh[j][0]) : "r"(sBh + ro));
                asm volatile("ld.shared.b32 %0, [%1];" : "=r"(Bfh[j][1]) : "r"(sBh + ro + 16));
                asm volatile("ld.shared.b32 %0, [%1];" : "=r"(Bfl[j][0]) : "r"(sBl + ro));
                asm volatile("ld.shared.b32 %0, [%1];" : "=r"(Bfl[j][1]) : "r"(sBl + ro + 16));
            }
#pragma unroll
            for (int i = 0; i < 4; ++i)
#pragma unroll
                for (int j = 0; j < 8; ++j) {
                    MMA_BF16(acc[i][j], Afh[i], Bfh[j]);
                    MMA_BF16(acc[i][j], Afh[i], Bfl[j]);
                    MMA_BF16(acc[i][j], Afl[i], Bfh[j]);
                }
        }
        __syncthreads();
    }

    // Epilogue: fp32 direct store
#pragma unroll
    for (int i = 0; i < 4; ++i) {
        int row = m0 + warp_m * 64 + i * 16 + g;
#pragma unroll
        for (int j = 0; j < 8; ++j) {
            int col = n0 + warp_n * 64 + j * 8 + tig * 2;
            *(float2*)&C[(size_t)row * N + col] =
                make_float2(acc[i][j][0], acc[i][j][1]);
            *(float2*)&C[(size_t)(row + 8) * N + col] =
                make_float2(acc[i][j][2], acc[i][j][3]);
        }
    }
}

// ---------------------------------------------------------------------------
// RoPE applied in place to q,k parts of g_qkv.
// ---------------------------------------------------------------------------
__global__ void rope_kernel(float* __restrict__ qkv,
                            const float* __restrict__ cosb,
                            const float* __restrict__ sinb) {
    int idx = blockIdx.x * blockDim.x + threadIdx.x;
    int pair = idx & 1023;
    int tok  = idx >> 10;
    if (tok >= NTOK) return;
    int t = tok & (T_SEQ - 1);
    int sel  = pair >> 9;
    int w    = pair & 511;
    int h    = w >> 5;
    int lane = w & 31;
    int f = sel * DMODEL + h * DHEAD + lane;
    float* p = qkv + (size_t)tok * QKV_F;
    float x1 = p[f];
    float x2 = p[f + 32];
    float c1 = cosb[t * DHEAD + lane];
    float s1 = sinb[t * DHEAD + lane];
    float c2 = cosb[t * DHEAD + lane + 32];
    float s2 = sinb[t * DHEAD + lane + 32];
    p[f]      = x1 * c1 - x2 * s1;
    p[f + 32] = x2 * c2 + x1 * s2;
}

// ---------------------------------------------------------------------------
// Sliding-window attention (fp32), epilogue emits bf16 hi/lo for GEMM2.
// ---------------------------------------------------------------------------
#define ATTN_SMEM (64 * (65 + 68 + 68 + 65) * 4)

__global__ __launch_bounds__(256)
void attn_kernel(const float* __restrict__ qkv,
                 __nv_bfloat16* __restrict__ ahi,
                 __nv_bfloat16* __restrict__ alo) {
    extern __shared__ float sm[];
    float (*Qs)[65]  = (float(*)[65])(sm);
    float (*Kst)[68] = (float(*)[68])(sm + 64 * 65);
    float (*Vs)[68]  = (float(*)[68])(sm + 64 * 65 + 64 * 68);
    float (*Ps)[65]  = (float(*)[65])(sm + 64 * 65 + 2 * 64 * 68);

    const int qb = blockIdx.x;
    const int h  = blockIdx.y;
    const int b  = blockIdx.z;
    const int q0 = qb * 64;
    const int tid = threadIdx.x;
    const int qg = tid >> 3;
    const int kg = tid & 7;

    const float scale = 0.125f;

    for (int l = tid; l < 64 * 16; l += 256) {
        int r = l >> 4, c = (l & 15) * 4;
        float4 v = *(const float4*)&qkv[((size_t)(b * T_SEQ + q0 + r)) * QKV_F + h * DHEAD + c];
        Qs[r][c]     = v.x * scale; Qs[r][c + 1] = v.y * scale;
        Qs[r][c + 2] = v.z * scale; Qs[r][c + 3] = v.w * scale;
    }

    float m[2]    = {-1e30f, -1e30f};
    float lsum[2] = {0.f, 0.f};
    float acc[2][8];
#pragma unroll
    for (int i = 0; i < 2; i++)
#pragma unroll
        for (int j = 0; j < 8; j++) acc[i][j] = 0.f;

    int lo = max(0, q0 - (WINDOW - 1)) >> 6;

    for (int kc = lo; kc <= qb; kc++) {
        const int k0 = kc * 64;
        __syncthreads();
        for (int l = tid; l < 64 * 16; l += 256) {
            int r = l >> 4, c = (l & 15) * 4;
            const float* bp = &qkv[((size_t)(b * T_SEQ + k0 + r)) * QKV_F + h * DHEAD + c];
            float4 kv = *(const float4*)(bp + DMODEL);
            Kst[c + 0][r] = kv.x; Kst[c + 1][r] = kv.y;
            Kst[c + 2][r] = kv.z; Kst[c + 3][r] = kv.w;
            float4 vv = *(const float4*)(bp + 2 * DMODEL);
            Vs[r][c] = vv.x; Vs[r][c + 1] = vv.y; Vs[r][c + 2] = vv.z; Vs[r][c + 3] = vv.w;
        }
        __syncthreads();

        float s[2][8];
#pragma unroll
        for (int i = 0; i < 2; i++)
#pragma unroll
            for (int j = 0; j < 8; j++) s[i][j] = 0.f;

#pragma unroll 8
        for (int d = 0; d < 64; d++) {
            float kr[8];
            *(float4*)&kr[0] = *(const float4*)&Kst[d][kg * 8];
            *(float4*)&kr[4] = *(const float4*)&Kst[d][kg * 8 + 4];
#pragma unroll
            for (int i = 0; i < 2; i++) {
                float qv = Qs[qg * 2 + i][d];
#pragma unroll
                for (int j = 0; j < 8; j++) s[i][j] += qv * kr[j];
            }
        }

#pragma unroll
        for (int i = 0; i < 2; i++) {
            int i_abs = q0 + qg * 2 + i;
            float cmax = -1e30f;
#pragma unroll
            for (int j = 0; j < 8; j++) {
                int j_abs = k0 + kg * 8 + j;
                bool ok = (j_abs <= i_abs) && (j_abs >= i_abs - (WINDOW - 1));
                if (!ok) s[i][j] = -1e30f;
                cmax = fmaxf(cmax, s[i][j]);
            }
            cmax = fmaxf(cmax, __shfl_xor_sync(0xffffffffu, cmax, 1));
            cmax = fmaxf(cmax, __shfl_xor_sync(0xffffffffu, cmax, 2));
            cmax = fmaxf(cmax, __shfl_xor_sync(0xffffffffu, cmax, 4));
            float mnew = fmaxf(m[i], cmax);
            float corr = __expf(m[i] - mnew);
            float ps = 0.f;
#pragma unroll
            for (int j = 0; j < 8; j++) {
                float p = (s[i][j] > -5e29f) ? __expf(s[i][j] - mnew) : 0.f;
                s[i][j] = p;
                ps += p;
            }
            ps += __shfl_xor_sync(0xffffffffu, ps, 1);
            ps += __shfl_xor_sync(0xffffffffu, ps, 2);
            ps += __shfl_xor_sync(0xffffffffu, ps, 4);
            lsum[i] = lsum[i] * corr + ps;
            m[i] = mnew;
#pragma unroll
            for (int j = 0; j < 8; j++) {
                acc[i][j] *= corr;
                Ps[qg * 2 + i][kg * 8 + j] = s[i][j];
            }
        }
        __syncwarp();

#pragma unroll 8
        for (int k = 0; k < 64; k++) {
            float vr[8];
            *(float4*)&vr[0] = *(const float4*)&Vs[k][kg * 8];
            *(float4*)&vr[4] = *(const float4*)&Vs[k][kg * 8 + 4];
#pragma unroll
            for (int i = 0; i < 2; i++) {
                float p = Ps[qg * 2 + i][k];
#pragma unroll
                for (int j = 0; j < 8; j++) acc[i][j] += p * vr[j];
            }
        }
    }

#pragma unroll
    for (int i = 0; i < 2; i++) {
        float inv = 1.f / lsum[i];
        __align__(16) __nv_bfloat16 hv[8], lv[8];
#pragma unroll
        for (int j = 0; j < 8; j++) {
            float v = acc[i][j] * inv;
            split1(v, hv[j], lv[j]);
        }
        size_t bidx = ((size_t)(b * T_SEQ + q0 + qg * 2 + i)) * DMODEL + h * DHEAD + kg * 8;
        *(uint4*)&ahi[bidx] = *(uint4*)hv;
        *(uint4*)&alo[bidx] = *(uint4*)lv;
    }
}

// ---------------------------------------------------------------------------
// Launch
// ---------------------------------------------------------------------------
extern "C" void kernel_launch(void* const* d_in, const int* in_sizes, int n_in,
                              void* d_out, int out_size) {
    const float* x     = (const float*)d_in[0];
    const float* cosb  = (const float*)d_in[1];
    const float* sinb  = (const float*)d_in[2];
    const float* qkv_w = (const float*)d_in[3];
    const float* out_w = (const float*)d_in[4];
    float* out = (float*)d_out;

    float *qkv = nullptr;
    __nv_bfloat16 *xhi, *xlo, *whi, *wlo, *ohi, *olo, *ahi, *alo;
    cudaGetSymbolAddress((void**)&qkv, g_qkv);
    cudaGetSymbolAddress((void**)&xhi, g_xhi);
    cudaGetSymbolAddress((void**)&xlo, g_xlo);
    cudaGetSymbolAddress((void**)&whi, g_whi);
    cudaGetSymbolAddress((void**)&wlo, g_wlo);
    cudaGetSymbolAddress((void**)&ohi, g_ohi);
    cudaGetSymbolAddress((void**)&olo, g_olo);
    cudaGetSymbolAddress((void**)&ahi, g_ahi);
    cudaGetSymbolAddress((void**)&alo, g_alo);

    cudaFuncSetAttribute(gemm_hmma_x3, cudaFuncAttributeMaxDynamicSharedMemorySize, GEMM_SMEM);
    cudaFuncSetAttribute(attn_kernel, cudaFuncAttributeMaxDynamicSharedMemorySize, ATTN_SMEM);

    // 0) Split inputs/weights into bf16 hi/lo
    split_kernel<<<(NTOK * DMODEL / 4 + 255) / 256, 256>>>(x, xhi, xlo, NTOK * DMODEL / 4);
    split_kernel<<<(QKV_F * DMODEL / 4 + 255) / 256, 256>>>(qkv_w, whi, wlo, QKV_F * DMODEL / 4);
    split_kernel<<<(DMODEL * DMODEL / 4 + 255) / 256, 256>>>(out_w, ohi, olo, DMODEL * DMODEL / 4);

    // 1) QKV projection (HMMA bf16x3): [8192,3072] = x @ qkv_w^T
    {
        dim3 grid(QKV_F / 256, NTOK / 128);
        gemm_hmma_x3<<<grid, 256, GEMM_SMEM>>>(xhi, xlo, whi, wlo, qkv, QKV_F);
    }
    // 2) RoPE on q,k (fp32, in place)
    rope_kernel<<<(NTOK * 1024) / 256, 256>>>(qkv, cosb, sinb);
    // 3) Sliding-window attention (fp32 in, bf16 hi/lo out)
    {
        dim3 grid(T_SEQ / 64, NHEADS, BATCH);
        attn_kernel<<<grid, 256, ATTN_SMEM>>>(qkv, ahi, alo);
    }
    // 4) Output projection (HMMA bf16x3): [8192,1024] = attn @ out_w^T
    {
        dim3 grid(DMODEL / 256, NTOK / 128);
        gemm_hmma_x3<<<grid, 256, GEMM_SMEM>>>(ahi, alo, ohi, olo, out, DMODEL);
    }
}

// round 6
// speedup vs baseline: 1.5985x; 1.0168x over previous
#include <cuda_runtime.h>
#include <cuda_bf16.h>
#include <math.h>
#include <stdint.h>

// Problem constants
#define BATCH 4
#define T_SEQ 2048
#define DMODEL 1024
#define NHEADS 16
#define DHEAD 64
#define WINDOW 256
#define NTOK (BATCH * T_SEQ)          // 8192
#define QKV_F (3 * DMODEL)            // 3072
#define KDIM 1024

// Scratch (device globals; allocation in kernel_launch is forbidden)
__device__ float g_qkv[(size_t)NTOK * QKV_F];
__device__ __nv_bfloat16 g_xhi[(size_t)NTOK * DMODEL];
__device__ __nv_bfloat16 g_xlo[(size_t)NTOK * DMODEL];
__device__ __nv_bfloat16 g_whi[(size_t)QKV_F * DMODEL];
__device__ __nv_bfloat16 g_wlo[(size_t)QKV_F * DMODEL];
__device__ __nv_bfloat16 g_ohi[(size_t)DMODEL * DMODEL];
__device__ __nv_bfloat16 g_olo[(size_t)DMODEL * DMODEL];
__device__ __nv_bfloat16 g_ahi[(size_t)NTOK * DMODEL];
__device__ __nv_bfloat16 g_alo[(size_t)NTOK * DMODEL];

// ---------------------------------------------------------------------------
// Helpers
// ---------------------------------------------------------------------------
__device__ __forceinline__ void split1(float x, __nv_bfloat16& h, __nv_bfloat16& l) {
    h = __float2bfloat16(x);
    l = __float2bfloat16(x - __bfloat162float(h));
}

__global__ void split_kernel(const float* __restrict__ in,
                             __nv_bfloat16* __restrict__ hi,
                             __nv_bfloat16* __restrict__ lo, int n4) {
    int i = blockIdx.x * 256 + threadIdx.x;
    if (i >= n4) return;
    float4 v = ((const float4*)in)[i];
    __align__(8) __nv_bfloat16 h4[4], l4[4];
    split1(v.x, h4[0], l4[0]); split1(v.y, h4[1], l4[1]);
    split1(v.z, h4[2], l4[2]); split1(v.w, h4[3], l4[3]);
    ((uint2*)hi)[i] = *(uint2*)h4;
    ((uint2*)lo)[i] = *(uint2*)l4;
}

__device__ __forceinline__ void cp_async16(uint32_t dst, const void* src) {
    asm volatile("cp.async.cg.shared.global [%0], [%1], 16;" :: "r"(dst), "l"(src) : "memory");
}
__device__ __forceinline__ void cp_commit() {
    asm volatile("cp.async.commit_group;" ::: "memory");
}
template <int N>
__device__ __forceinline__ void cp_wait() {
    asm volatile("cp.async.wait_group %0;" :: "n"(N) : "memory");
}

#define MMA_BF16(d, a, b)                                                       \
    asm volatile("mma.sync.aligned.m16n8k16.row.col.f32.bf16.bf16.f32 "         \
                 "{%0,%1,%2,%3}, {%4,%5,%6,%7}, {%8,%9}, {%0,%1,%2,%3};"        \
                 : "+f"((d)[0]), "+f"((d)[1]), "+f"((d)[2]), "+f"((d)[3])       \
                 : "r"((a)[0]), "r"((a)[1]), "r"((a)[2]), "r"((a)[3]),          \
                   "r"((b)[0]), "r"((b)[1]))

// ---------------------------------------------------------------------------
// bf16x3 HMMA GEMM: C[M,N] = (Ah+Al)[M,K] * ((Bh+Bl)[N,K])^T, fp32 accum.
// Tile 128x128, BK=32, 8 warps (2x4), warp tile 64x32, double-buffer cp.async.
// __launch_bounds__(256, 2): cap regs at 128 so TWO CTAs co-reside per SM —
// barrier drains in one CTA are covered by the other CTA's MMA stream.
// ---------------------------------------------------------------------------
#define ROWB 80                     // smem row stride bytes (40 bf16)
#define PART (128 * ROWB)           // 10240 bytes per part
#define STAGE (4 * PART)            // 40960 bytes
#define GEMM_SMEM (2 * STAGE)       // 81920

__global__ __launch_bounds__(256, 2)
void gemm_hmma_x3(const __nv_bfloat16* __restrict__ Ah, const __nv_bfloat16* __restrict__ Al,
                  const __nv_bfloat16* __restrict__ Bh, const __nv_bfloat16* __restrict__ Bl,
                  float* __restrict__ C, int N) {
    extern __shared__ __align__(16) char dynsm[];
    const int tid  = threadIdx.x;
    const int warp = tid >> 5, lane = tid & 31;
    const int g = lane >> 2, tig = lane & 3;
    const int warp_m = warp >> 2;          // 0..1
    const int warp_n = warp & 3;           // 0..3
    const int m0 = blockIdx.y * 128;
    const int n0 = blockIdx.x * 128;

    uint32_t smbase;
    asm("{ .reg .u64 t; cvta.to.shared.u64 t, %1; cvt.u32.u64 %0, t; }"
        : "=r"(smbase) : "l"(dynsm));

    const __nv_bfloat16* Ah_ = Ah + (size_t)m0 * KDIM;
    const __nv_bfloat16* Al_ = Al + (size_t)m0 * KDIM;
    const __nv_bfloat16* Bh_ = Bh + (size_t)n0 * KDIM;
    const __nv_bfloat16* Bl_ = Bl + (size_t)n0 * KDIM;

    auto load_stage = [&](int c) {
        const int st = c & 1;
        const int k0 = c * 32;
        const uint32_t sb = smbase + st * STAGE;
#pragma unroll
        for (int l = 0; l < 2; ++l) {
            int idx = tid + l * 256;
            int r = idx >> 2, c8 = idx & 3;
            size_t go = (size_t)r * KDIM + k0 + c8 * 8;
            uint32_t so = (uint32_t)(r * ROWB + c8 * 16);
            cp_async16(sb + so,            Ah_ + go);
            cp_async16(sb + PART + so,     Al_ + go);
            cp_async16(sb + 2 * PART + so, Bh_ + go);
            cp_async16(sb + 3 * PART + so, Bl_ + go);
        }
    };

    float acc[4][4][4];
#pragma unroll
    for (int i = 0; i < 4; i++)
#pragma unroll
        for (int j = 0; j < 4; j++)
#pragma unroll
            for (int v = 0; v < 4; v++) acc[i][j][v] = 0.f;

    load_stage(0);
    cp_commit();

    const int NC = KDIM / 32;   // 32 chunks
    for (int c = 0; c < NC; ++c) {
        if (c + 1 < NC) { load_stage(c + 1); cp_commit(); cp_wait<1>(); }
        else           { cp_wait<0>(); }
        __syncthreads();

        const uint32_t sb  = smbase + (c & 1) * STAGE;
        const uint32_t sAh = sb,            sAl = sb + PART;
        const uint32_t sBh = sb + 2 * PART, sBl = sb + 3 * PART;

#pragma unroll
        for (int s = 0; s < 2; ++s) {
            const int ksb = s * 32 + tig * 4;
            uint32_t Afh[4][4], Afl[4][4], Bfh[4][2], Bfl[4][2];
#pragma unroll
            for (int i = 0; i < 4; ++i) {
                uint32_t ro = (uint32_t)((warp_m * 64 + i * 16 + g) * ROWB + ksb);
                asm volatile("ld.shared.b32 %0, [%1];" : "=r"(Afh[i][0]) : "r"(sAh + ro));
                asm volatile("ld.shared.b32 %0, [%1];" : "=r"(Afh[i][1]) : "r"(sAh + ro + 8 * ROWB));
                asm volatile("ld.shared.b32 %0, [%1];" : "=r"(Afh[i][2]) : "r"(sAh + ro + 16));
                asm volatile("ld.shared.b32 %0, [%1];" : "=r"(Afh[i][3]) : "r"(sAh + ro + 8 * ROWB + 16));
                asm volatile("ld.shared.b32 %0, [%1];" : "=r"(Afl[i][0]) : "r"(sAl + ro));
                asm volatile("ld.shared.b32 %0, [%1];" : "=r"(Afl[i][1]) : "r"(sAl + ro + 8 * ROWB));
                asm volatile("ld.shared.b32 %0, [%1];" : "=r"(Afl[i][2]) : "r"(sAl + ro + 16));
                asm volatile("ld.shared.b32 %0, [%1];" : "=r"(Afl[i][3]) : "r"(sAl + ro + 8 * ROWB + 16));
            }
#pragma unroll
            for (int j = 0; j < 4; ++j) {
                uint32_t ro = (uint32_t)((warp_n * 32 + j * 8 + g) * ROWB + ksb);
                asm volatile("ld.shared.b32 %0, [%1];" : "=r"(Bfh[j][0]) : "r"(sBh + ro));
                asm volatile("ld.shared.b32 %0, [%1];" : "=r"(Bfh[j][1]) : "r"(sBh + ro + 16));
                asm volatile("ld.shared.b32 %0, [%1];" : "=r"(Bfl[j][0]) : "r"(sBl + ro));
                asm volatile("ld.shared.b32 %0, [%1];" : "=r"(Bfl[j][1]) : "r"(sBl + ro + 16));
            }
#pragma unroll
            for (int i = 0; i < 4; ++i)
#pragma unroll
                for (int j = 0; j < 4; ++j) {
                    MMA_BF16(acc[i][j], Afh[i], Bfh[j]);
                    MMA_BF16(acc[i][j], Afh[i], Bfl[j]);
                    MMA_BF16(acc[i][j], Afl[i], Bfh[j]);
                }
        }
        __syncthreads();
    }

    // Epilogue: fp32 direct store
#pragma unroll
    for (int i = 0; i < 4; ++i) {
        int row = m0 + warp_m * 64 + i * 16 + g;
#pragma unroll
        for (int j = 0; j < 4; ++j) {
            int col = n0 + warp_n * 32 + j * 8 + tig * 2;
            *(float2*)&C[(size_t)row * N + col] =
                make_float2(acc[i][j][0], acc[i][j][1]);
            *(float2*)&C[(size_t)(row + 8) * N + col] =
                make_float2(acc[i][j][2], acc[i][j][3]);
        }
    }
}

// ---------------------------------------------------------------------------
// RoPE applied in place to q,k parts of g_qkv.
// ---------------------------------------------------------------------------
__global__ void rope_kernel(float* __restrict__ qkv,
                            const float* __restrict__ cosb,
                            const float* __restrict__ sinb) {
    int idx = blockIdx.x * blockDim.x + threadIdx.x;
    int pair = idx & 1023;
    int tok  = idx >> 10;
    if (tok >= NTOK) return;
    int t = tok & (T_SEQ - 1);
    int sel  = pair >> 9;
    int w    = pair & 511;
    int h    = w >> 5;
    int lane = w & 31;
    int f = sel * DMODEL + h * DHEAD + lane;
    float* p = qkv + (size_t)tok * QKV_F;
    float x1 = p[f];
    float x2 = p[f + 32];
    float c1 = cosb[t * DHEAD + lane];
    float s1 = sinb[t * DHEAD + lane];
    float c2 = cosb[t * DHEAD + lane + 32];
    float s2 = sinb[t * DHEAD + lane + 32];
    p[f]      = x1 * c1 - x2 * s1;
    p[f + 32] = x2 * c2 + x1 * s2;
}

// ---------------------------------------------------------------------------
// Sliding-window attention (fp32), epilogue emits bf16 hi/lo for GEMM2.
// ---------------------------------------------------------------------------
#define ATTN_SMEM (64 * (65 + 68 + 68 + 65) * 4)

__global__ __launch_bounds__(256)
void attn_kernel(const float* __restrict__ qkv,
                 __nv_bfloat16* __restrict__ ahi,
                 __nv_bfloat16* __restrict__ alo) {
    extern __shared__ float sm[];
    float (*Qs)[65]  = (float(*)[65])(sm);
    float (*Kst)[68] = (float(*)[68])(sm + 64 * 65);
    float (*Vs)[68]  = (float(*)[68])(sm + 64 * 65 + 64 * 68);
    float (*Ps)[65]  = (float(*)[65])(sm + 64 * 65 + 2 * 64 * 68);

    const int qb = blockIdx.x;
    const int h  = blockIdx.y;
    const int b  = blockIdx.z;
    const int q0 = qb * 64;
    const int tid = threadIdx.x;
    const int qg = tid >> 3;
    const int kg = tid & 7;

    const float scale = 0.125f;

    for (int l = tid; l < 64 * 16; l += 256) {
        int r = l >> 4, c = (l & 15) * 4;
        float4 v = *(const float4*)&qkv[((size_t)(b * T_SEQ + q0 + r)) * QKV_F + h * DHEAD + c];
        Qs[r][c]     = v.x * scale; Qs[r][c + 1] = v.y * scale;
        Qs[r][c + 2] = v.z * scale; Qs[r][c + 3] = v.w * scale;
    }

    float m[2]    = {-1e30f, -1e30f};
    float lsum[2] = {0.f, 0.f};
    float acc[2][8];
#pragma unroll
    for (int i = 0; i < 2; i++)
#pragma unroll
        for (int j = 0; j < 8; j++) acc[i][j] = 0.f;

    int lo = max(0, q0 - (WINDOW - 1)) >> 6;

    for (int kc = lo; kc <= qb; kc++) {
        const int k0 = kc * 64;
        __syncthreads();
        for (int l = tid; l < 64 * 16; l += 256) {
            int r = l >> 4, c = (l & 15) * 4;
            const float* bp = &qkv[((size_t)(b * T_SEQ + k0 + r)) * QKV_F + h * DHEAD + c];
            float4 kv = *(const float4*)(bp + DMODEL);
            Kst[c + 0][r] = kv.x; Kst[c + 1][r] = kv.y;
            Kst[c + 2][r] = kv.z; Kst[c + 3][r] = kv.w;
            float4 vv = *(const float4*)(bp + 2 * DMODEL);
            Vs[r][c] = vv.x; Vs[r][c + 1] = vv.y; Vs[r][c + 2] = vv.z; Vs[r][c + 3] = vv.w;
        }
        __syncthreads();

        float s[2][8];
#pragma unroll
        for (int i = 0; i < 2; i++)
#pragma unroll
            for (int j = 0; j < 8; j++) s[i][j] = 0.f;

#pragma unroll 8
        for (int d = 0; d < 64; d++) {
            float kr[8];
            *(float4*)&kr[0] = *(const float4*)&Kst[d][kg * 8];
            *(float4*)&kr[4] = *(const float4*)&Kst[d][kg * 8 + 4];
#pragma unroll
            for (int i = 0; i < 2; i++) {
                float qv = Qs[qg * 2 + i][d];
#pragma unroll
                for (int j = 0; j < 8; j++) s[i][j] += qv * kr[j];
            }
        }

#pragma unroll
        for (int i = 0; i < 2; i++) {
            int i_abs = q0 + qg * 2 + i;
            float cmax = -1e30f;
#pragma unroll
            for (int j = 0; j < 8; j++) {
                int j_abs = k0 + kg * 8 + j;
                bool ok = (j_abs <= i_abs) && (j_abs >= i_abs - (WINDOW - 1));
                if (!ok) s[i][j] = -1e30f;
                cmax = fmaxf(cmax, s[i][j]);
            }
            cmax = fmaxf(cmax, __shfl_xor_sync(0xffffffffu, cmax, 1));
            cmax = fmaxf(cmax, __shfl_xor_sync(0xffffffffu, cmax, 2));
            cmax = fmaxf(cmax, __shfl_xor_sync(0xffffffffu, cmax, 4));
            float mnew = fmaxf(m[i], cmax);
            float corr = __expf(m[i] - mnew);
            float ps = 0.f;
#pragma unroll
            for (int j = 0; j < 8; j++) {
                float p = (s[i][j] > -5e29f) ? __expf(s[i][j] - mnew) : 0.f;
                s[i][j] = p;
                ps += p;
            }
            ps += __shfl_xor_sync(0xffffffffu, ps, 1);
            ps += __shfl_xor_sync(0xffffffffu, ps, 2);
            ps += __shfl_xor_sync(0xffffffffu, ps, 4);
            lsum[i] = lsum[i] * corr + ps;
            m[i] = mnew;
#pragma unroll
            for (int j = 0; j < 8; j++) {
                acc[i][j] *= corr;
                Ps[qg * 2 + i][kg * 8 + j] = s[i][j];
            }
        }
        __syncwarp();

#pragma unroll 8
        for (int k = 0; k < 64; k++) {
            float vr[8];
            *(float4*)&vr[0] = *(const float4*)&Vs[k][kg * 8];
            *(float4*)&vr[4] = *(const float4*)&Vs[k][kg * 8 + 4];
#pragma unroll
            for (int i = 0; i < 2; i++) {
                float p = Ps[qg * 2 + i][k];
#pragma unroll
                for (int j = 0; j < 8; j++) acc[i][j] += p * vr[j];
            }
        }
    }

#pragma unroll
    for (int i = 0; i < 2; i++) {
        float inv = 1.f / lsum[i];
        __align__(16) __nv_bfloat16 hv[8], lv[8];
#pragma unroll
        for (int j = 0; j < 8; j++) {
            float v = acc[i][j] * inv;
            split1(v, hv[j], lv[j]);
        }
        size_t bidx = ((size_t)(b * T_SEQ + q0 + qg * 2 + i)) * DMODEL + h * DHEAD + kg * 8;
        *(uint4*)&ahi[bidx] = *(uint4*)hv;
        *(uint4*)&alo[bidx] = *(uint4*)lv;
    }
}

// ---------------------------------------------------------------------------
// Launch
// ---------------------------------------------------------------------------
extern "C" void kernel_launch(void* const* d_in, const int* in_sizes, int n_in,
                              void* d_out, int out_size) {
    const float* x     = (const float*)d_in[0];
    const float* cosb  = (const float*)d_in[1];
    const float* sinb  = (const float*)d_in[2];
    const float* qkv_w = (const float*)d_in[3];
    const float* out_w = (const float*)d_in[4];
    float* out = (float*)d_out;

    float *qkv = nullptr;
    __nv_bfloat16 *xhi, *xlo, *whi, *wlo, *ohi, *olo, *ahi, *alo;
    cudaGetSymbolAddress((void**)&qkv, g_qkv);
    cudaGetSymbolAddress((void**)&xhi, g_xhi);
    cudaGetSymbolAddress((void**)&xlo, g_xlo);
    cudaGetSymbolAddress((void**)&whi, g_whi);
    cudaGetSymbolAddress((void**)&wlo, g_wlo);
    cudaGetSymbolAddress((void**)&ohi, g_ohi);
    cudaGetSymbolAddress((void**)&olo, g_olo);
    cudaGetSymbolAddress((void**)&ahi, g_ahi);
    cudaGetSymbolAddress((void**)&alo, g_alo);

    cudaFuncSetAttribute(gemm_hmma_x3, cudaFuncAttributeMaxDynamicSharedMemorySize, GEMM_SMEM);
    cudaFuncSetAttribute(attn_kernel, cudaFuncAttributeMaxDynamicSharedMemorySize, ATTN_SMEM);

    // 0) Split inputs/weights into bf16 hi/lo
    split_kernel<<<(NTOK * DMODEL / 4 + 255) / 256, 256>>>(x, xhi, xlo, NTOK * DMODEL / 4);
    split_kernel<<<(QKV_F * DMODEL / 4 + 255) / 256, 256>>>(qkv_w, whi, wlo, QKV_F * DMODEL / 4);
    split_kernel<<<(DMODEL * DMODEL / 4 + 255) / 256, 256>>>(out_w, ohi, olo, DMODEL * DMODEL / 4);

    // 1) QKV projection (HMMA bf16x3): [8192,3072] = x @ qkv_w^T
    {
        dim3 grid(QKV_F / 128, NTOK / 128);
        gemm_hmma_x3<<<grid, 256, GEMM_SMEM>>>(xhi, xlo, whi, wlo, qkv, QKV_F);
    }
    // 2) RoPE on q,k (fp32, in place)
    rope_kernel<<<(NTOK * 1024) / 256, 256>>>(qkv, cosb, sinb);
    // 3) Sliding-window attention (fp32 in, bf16 hi/lo out)
    {
        dim3 grid(T_SEQ / 64, NHEADS, BATCH);
        attn_kernel<<<grid, 256, ATTN_SMEM>>>(qkv, ahi, alo);
    }
    // 4) Output projection (HMMA bf16x3): [8192,1024] = attn @ out_w^T
    {
        dim3 grid(DMODEL / 128, NTOK / 128);
        gemm_hmma_x3<<<grid, 256, GEMM_SMEM>>>(ahi, alo, ohi, olo, out, DMODEL);
    }
}

// round 7
// speedup vs baseline: 2.6541x; 1.6603x over previous
#include <cuda_runtime.h>
#include <cuda_bf16.h>
#include <math.h>
#include <stdint.h>

// Problem constants
#define BATCH 4
#define T_SEQ 2048
#define DMODEL 1024
#define NHEADS 16
#define DHEAD 64
#define WINDOW 256
#define NTOK (BATCH * T_SEQ)          // 8192
#define QKV_F (3 * DMODEL)            // 3072
#define KDIM 1024
#define NBH (BATCH * NHEADS)          // 64

typedef __nv_bfloat16 bf16t;

// Scratch (device globals; allocation in kernel_launch is forbidden)
__device__ float g_qkv[(size_t)NTOK * QKV_F];
__device__ bf16t g_xhi[(size_t)NTOK * DMODEL];
__device__ bf16t g_xlo[(size_t)NTOK * DMODEL];
__device__ bf16t g_whi[(size_t)QKV_F * DMODEL];
__device__ bf16t g_wlo[(size_t)QKV_F * DMODEL];
__device__ bf16t g_ohi[(size_t)DMODEL * DMODEL];
__device__ bf16t g_olo[(size_t)DMODEL * DMODEL];
__device__ bf16t g_ahi[(size_t)NTOK * DMODEL];
__device__ bf16t g_alo[(size_t)NTOK * DMODEL];
// Head-major [b][h][t][d] bf16 hi/lo for attention
__device__ bf16t g_qh[(size_t)NBH * T_SEQ * DHEAD];
__device__ bf16t g_ql[(size_t)NBH * T_SEQ * DHEAD];
__device__ bf16t g_kh[(size_t)NBH * T_SEQ * DHEAD];
__device__ bf16t g_kl[(size_t)NBH * T_SEQ * DHEAD];
__device__ bf16t g_vh[(size_t)NBH * T_SEQ * DHEAD];
__device__ bf16t g_vl[(size_t)NBH * T_SEQ * DHEAD];

// ---------------------------------------------------------------------------
// Helpers
// ---------------------------------------------------------------------------
__device__ __forceinline__ void split1(float x, bf16t& h, bf16t& l) {
    h = __float2bfloat16(x);
    l = __float2bfloat16(x - __bfloat162float(h));
}
__device__ __forceinline__ uint32_t pack_bf16(float a, float b) {
    // word = {lo: bf16(a), hi: bf16(b)}
    uint32_t r;
    asm("cvt.rn.bf16x2.f32 %0, %1, %2;" : "=r"(r) : "f"(b), "f"(a));
    return r;
}

__global__ void split_kernel(const float* __restrict__ in,
                             bf16t* __restrict__ hi,
                             bf16t* __restrict__ lo, int n4) {
    int i = blockIdx.x * 256 + threadIdx.x;
    if (i >= n4) return;
    float4 v = ((const float4*)in)[i];
    __align__(8) bf16t h4[4], l4[4];
    split1(v.x, h4[0], l4[0]); split1(v.y, h4[1], l4[1]);
    split1(v.z, h4[2], l4[2]); split1(v.w, h4[3], l4[3]);
    ((uint2*)hi)[i] = *(uint2*)h4;
    ((uint2*)lo)[i] = *(uint2*)l4;
}

__device__ __forceinline__ void cp_async16(uint32_t dst, const void* src) {
    asm volatile("cp.async.cg.shared.global [%0], [%1], 16;" :: "r"(dst), "l"(src) : "memory");
}
__device__ __forceinline__ void cp_commit() {
    asm volatile("cp.async.commit_group;" ::: "memory");
}
template <int N>
__device__ __forceinline__ void cp_wait() {
    asm volatile("cp.async.wait_group %0;" :: "n"(N) : "memory");
}

#define MMA_BF16(d, a, b)                                                       \
    asm volatile("mma.sync.aligned.m16n8k16.row.col.f32.bf16.bf16.f32 "         \
                 "{%0,%1,%2,%3}, {%4,%5,%6,%7}, {%8,%9}, {%0,%1,%2,%3};"        \
                 : "+f"((d)[0]), "+f"((d)[1]), "+f"((d)[2]), "+f"((d)[3])       \
                 : "r"((a)[0]), "r"((a)[1]), "r"((a)[2]), "r"((a)[3]),          \
                   "r"((b)[0]), "r"((b)[1]))

#define LDSM_X4(r0, r1, r2, r3, a)                                              \
    asm volatile("ldmatrix.sync.aligned.m8n8.x4.shared.b16 {%0,%1,%2,%3}, [%4];"\
                 : "=r"(r0), "=r"(r1), "=r"(r2), "=r"(r3) : "r"(a))
#define LDSM_X4T(r0, r1, r2, r3, a)                                             \
    asm volatile("ldmatrix.sync.aligned.m8n8.x4.trans.shared.b16 {%0,%1,%2,%3}, [%4];"\
                 : "=r"(r0), "=r"(r1), "=r"(r2), "=r"(r3) : "r"(a))

// ---------------------------------------------------------------------------
// bf16x3 HMMA GEMM (unchanged from R6): tile 128x128, BK=32, 2 CTAs/SM.
// ---------------------------------------------------------------------------
#define ROWB 80
#define PART (128 * ROWB)
#define STAGE (4 * PART)
#define GEMM_SMEM (2 * STAGE)

__global__ __launch_bounds__(256, 2)
void gemm_hmma_x3(const bf16t* __restrict__ Ah, const bf16t* __restrict__ Al,
                  const bf16t* __restrict__ Bh, const bf16t* __restrict__ Bl,
                  float* __restrict__ C, int N) {
    extern __shared__ __align__(16) char dynsm[];
    const int tid  = threadIdx.x;
    const int warp = tid >> 5, lane = tid & 31;
    const int g = lane >> 2, tig = lane & 3;
    const int warp_m = warp >> 2;
    const int warp_n = warp & 3;
    const int m0 = blockIdx.y * 128;
    const int n0 = blockIdx.x * 128;

    uint32_t smbase;
    asm("{ .reg .u64 t; cvta.to.shared.u64 t, %1; cvt.u32.u64 %0, t; }"
        : "=r"(smbase) : "l"(dynsm));

    const bf16t* Ah_ = Ah + (size_t)m0 * KDIM;
    const bf16t* Al_ = Al + (size_t)m0 * KDIM;
    const bf16t* Bh_ = Bh + (size_t)n0 * KDIM;
    const bf16t* Bl_ = Bl + (size_t)n0 * KDIM;

    auto load_stage = [&](int c) {
        const int st = c & 1;
        const int k0 = c * 32;
        const uint32_t sb = smbase + st * STAGE;
#pragma unroll
        for (int l = 0; l < 2; ++l) {
            int idx = tid + l * 256;
            int r = idx >> 2, c8 = idx & 3;
            size_t go = (size_t)r * KDIM + k0 + c8 * 8;
            uint32_t so = (uint32_t)(r * ROWB + c8 * 16);
            cp_async16(sb + so,            Ah_ + go);
            cp_async16(sb + PART + so,     Al_ + go);
            cp_async16(sb + 2 * PART + so, Bh_ + go);
            cp_async16(sb + 3 * PART + so, Bl_ + go);
        }
    };

    float acc[4][4][4];
#pragma unroll
    for (int i = 0; i < 4; i++)
#pragma unroll
        for (int j = 0; j < 4; j++)
#pragma unroll
            for (int v = 0; v < 4; v++) acc[i][j][v] = 0.f;

    load_stage(0);
    cp_commit();

    const int NC = KDIM / 32;
    for (int c = 0; c < NC; ++c) {
        if (c + 1 < NC) { load_stage(c + 1); cp_commit(); cp_wait<1>(); }
        else           { cp_wait<0>(); }
        __syncthreads();

        const uint32_t sb  = smbase + (c & 1) * STAGE;
        const uint32_t sAh = sb,            sAl = sb + PART;
        const uint32_t sBh = sb + 2 * PART, sBl = sb + 3 * PART;

#pragma unroll
        for (int s = 0; s < 2; ++s) {
            const int ksb = s * 32 + tig * 4;
            uint32_t Afh[4][4], Afl[4][4], Bfh[4][2], Bfl[4][2];
#pragma unroll
            for (int i = 0; i < 4; ++i) {
                uint32_t ro = (uint32_t)((warp_m * 64 + i * 16 + g) * ROWB + ksb);
                asm volatile("ld.shared.b32 %0, [%1];" : "=r"(Afh[i][0]) : "r"(sAh + ro));
                asm volatile("ld.shared.b32 %0, [%1];" : "=r"(Afh[i][1]) : "r"(sAh + ro + 8 * ROWB));
                asm volatile("ld.shared.b32 %0, [%1];" : "=r"(Afh[i][2]) : "r"(sAh + ro + 16));
                asm volatile("ld.shared.b32 %0, [%1];" : "=r"(Afh[i][3]) : "r"(sAh + ro + 8 * ROWB + 16));
                asm volatile("ld.shared.b32 %0, [%1];" : "=r"(Afl[i][0]) : "r"(sAl + ro));
                asm volatile("ld.shared.b32 %0, [%1];" : "=r"(Afl[i][1]) : "r"(sAl + ro + 8 * ROWB));
                asm volatile("ld.shared.b32 %0, [%1];" : "=r"(Afl[i][2]) : "r"(sAl + ro + 16));
                asm volatile("ld.shared.b32 %0, [%1];" : "=r"(Afl[i][3]) : "r"(sAl + ro + 8 * ROWB + 16));
            }
#pragma unroll
            for (int j = 0; j < 4; ++j) {
                uint32_t ro = (uint32_t)((warp_n * 32 + j * 8 + g) * ROWB + ksb);
                asm volatile("ld.shared.b32 %0, [%1];" : "=r"(Bfh[j][0]) : "r"(sBh + ro));
                asm volatile("ld.shared.b32 %0, [%1];" : "=r"(Bfh[j][1]) : "r"(sBh + ro + 16));
                asm volatile("ld.shared.b32 %0, [%1];" : "=r"(Bfl[j][0]) : "r"(sBl + ro));
                asm volatile("ld.shared.b32 %0, [%1];" : "=r"(Bfl[j][1]) : "r"(sBl + ro + 16));
            }
#pragma unroll
            for (int i = 0; i < 4; ++i)
#pragma unroll
                for (int j = 0; j < 4; ++j) {
                    MMA_BF16(acc[i][j], Afh[i], Bfh[j]);
                    MMA_BF16(acc[i][j], Afh[i], Bfl[j]);
                    MMA_BF16(acc[i][j], Afl[i], Bfh[j]);
                }
        }
        __syncthreads();
    }

#pragma unroll
    for (int i = 0; i < 4; ++i) {
        int row = m0 + warp_m * 64 + i * 16 + g;
#pragma unroll
        for (int j = 0; j < 4; ++j) {
            int col = n0 + warp_n * 32 + j * 8 + tig * 2;
            *(float2*)&C[(size_t)row * N + col] =
                make_float2(acc[i][j][0], acc[i][j][1]);
            *(float2*)&C[(size_t)(row + 8) * N + col] =
                make_float2(acc[i][j][2], acc[i][j][3]);
        }
    }
}

// ---------------------------------------------------------------------------
// RoPE + split to head-major bf16 hi/lo. Q gets 1/8 scale folded in.
// Thread handles one (tok, h, d<32): q pair, k pair, v pair.
// ---------------------------------------------------------------------------
__global__ void rope_split_kernel(const float* __restrict__ qkv,
                                  const float* __restrict__ cosb,
                                  const float* __restrict__ sinb) {
    int idx = blockIdx.x * 256 + threadIdx.x;
    if (idx >= NTOK * 512) return;
    int w = idx & 511, tok = idx >> 9;
    int h = w >> 5, d = w & 31;
    int t = tok & (T_SEQ - 1), b = tok >> 11;

    const float* p = qkv + (size_t)tok * QKV_F + h * 64 + d;
    float c1 = cosb[t * 64 + d],      s1 = sinb[t * 64 + d];
    float c2 = cosb[t * 64 + d + 32], s2 = sinb[t * 64 + d + 32];
    float q1 = p[0], q2 = p[32];
    float k1 = p[1024], k2 = p[1056];
    float v1 = p[2048], v2 = p[2080];
    float qr1 = (q1 * c1 - q2 * s1) * 0.125f;
    float qr2 = (q2 * c2 + q1 * s2) * 0.125f;
    float kr1 = k1 * c1 - k2 * s1;
    float kr2 = k2 * c2 + k1 * s2;

    size_t o = ((size_t)(b * NHEADS + h) * T_SEQ + t) * 64 + d;
    bf16t hv, lv;
    split1(qr1, hv, lv); g_qh[o] = hv;      g_ql[o] = lv;
    split1(qr2, hv, lv); g_qh[o + 32] = hv; g_ql[o + 32] = lv;
    split1(kr1, hv, lv); g_kh[o] = hv;      g_kl[o] = lv;
    split1(kr2, hv, lv); g_kh[o + 32] = hv; g_kl[o + 32] = lv;
    split1(v1,  hv, lv); g_vh[o] = hv;      g_vl[o] = lv;
    split1(v2,  hv, lv); g_vh[o + 32] = hv; g_vl[o + 32] = lv;
}

// ---------------------------------------------------------------------------
// Flash attention on HMMA (bf16x3). CTA = 64 queries x head x batch, 4 warps.
// Q frags register-resident; K via ldmatrix.x4; V via ldmatrix.x4.trans.
// SMEM rows 144B stride (bank = 4g -> conflict-free ldmatrix).
// ---------------------------------------------------------------------------
#define AT_ROWB 144
#define AT_PART (64 * AT_ROWB)             // 9216
#define AT_KV0  (2 * AT_PART)              // Q hi/lo first
#define AT_STAGE (4 * AT_PART)             // Kh,Kl,Vh,Vl
#define ATTN_SMEM (2 * AT_PART + 2 * AT_STAGE)   // 92160

__global__ __launch_bounds__(128, 2)
void attn_hmma(bf16t* __restrict__ ahi, bf16t* __restrict__ alo) {
    extern __shared__ __align__(16) char dynsm[];
    const int tid = threadIdx.x;
    const int warp = tid >> 5, lane = tid & 31;
    const int g = lane >> 2, tig = lane & 3;
    const int qb = blockIdx.x, h = blockIdx.y, b = blockIdx.z;
    const int q0 = qb * 64;
    const size_t headoff = (size_t)(b * NHEADS + h) * T_SEQ * 64;

    uint32_t smbase;
    asm("{ .reg .u64 t; cvta.to.shared.u64 t, %1; cvt.u32.u64 %0, t; }"
        : "=r"(smbase) : "l"(dynsm));
    const uint32_t smQh = smbase, smQl = smbase + AT_PART;

    // ---- async loaders ----
    auto load_q = [&]() {
#pragma unroll
        for (int l = 0; l < 4; ++l) {
            int idx = tid + l * 128;
            int r = idx >> 3, c8 = idx & 7;
            uint32_t so = (uint32_t)(r * AT_ROWB + c8 * 16);
            size_t go = headoff + (size_t)(q0 + r) * 64 + c8 * 8;
            cp_async16(smQh + so, g_qh + go);
            cp_async16(smQl + so, g_ql + go);
        }
    };
    auto load_kv = [&](int kc, int st) {
        const uint32_t sb = smbase + AT_KV0 + st * AT_STAGE;
#pragma unroll
        for (int l = 0; l < 4; ++l) {
            int idx = tid + l * 128;
            int r = idx >> 3, c8 = idx & 7;
            uint32_t so = (uint32_t)(r * AT_ROWB + c8 * 16);
            size_t go = headoff + (size_t)(kc * 64 + r) * 64 + c8 * 8;
            cp_async16(sb + so,               g_kh + go);
            cp_async16(sb + AT_PART + so,     g_kl + go);
            cp_async16(sb + 2 * AT_PART + so, g_vh + go);
            cp_async16(sb + 3 * AT_PART + so, g_vl + go);
        }
    };

    const int lo = (qb >= 4) ? qb - 4 : 0;
    const int nch = qb - lo + 1;

    load_q();
    load_kv(lo, 0);
    cp_commit();
    if (nch > 1) { load_kv(lo + 1, 1); cp_commit(); }

    // ldmatrix per-lane address offsets
    const int lrow = lane & 7;
    const int ltile = lane >> 3;           // 0..3
    const uint32_t qa_off = (uint32_t)((warp * 16 + (ltile & 1) * 8 + lrow) * AT_ROWB + (ltile >> 1) * 16);
    const uint32_t ka_row = (uint32_t)(((ltile & 1) * 8 + lrow) * AT_ROWB);     // + n-block*16row + kbytes
    const uint32_t va_row = (uint32_t)(((ltile & 1) * 8 + lrow) * AT_ROWB);     // + key-block + nbytes

    uint32_t qfh[4][4], qfl[4][4];
    float o[8][4];
#pragma unroll
    for (int j = 0; j < 8; ++j)
#pragma unroll
        for (int v = 0; v < 4; ++v) o[j][v] = 0.f;
    float m0 = -1e30f, m1 = -1e30f, l0 = 0.f, l1 = 0.f;
    const int i0 = q0 + warp * 16 + g, i1 = i0 + 8;

    for (int ci = 0; ci < nch; ++ci) {
        const int kc = lo + ci;
        if (ci == nch - 1) cp_wait<0>(); else cp_wait<1>();
        __syncthreads();

        if (ci == 0) {
#pragma unroll
            for (int s = 0; s < 4; ++s) {
                LDSM_X4(qfh[s][0], qfh[s][1], qfh[s][2], qfh[s][3], smQh + qa_off + s * 32);
                LDSM_X4(qfl[s][0], qfl[s][1], qfl[s][2], qfl[s][3], smQl + qa_off + s * 32);
            }
        }

        const uint32_t sb  = smbase + AT_KV0 + (ci & 1) * AT_STAGE;
        const uint32_t sKh = sb, sKl = sb + AT_PART;
        const uint32_t sVh = sb + 2 * AT_PART, sVl = sb + 3 * AT_PART;

        // ---- S = Q K^T ----
        float c[8][4];
#pragma unroll
        for (int j = 0; j < 8; ++j)
#pragma unroll
            for (int v = 0; v < 4; ++v) c[j][v] = 0.f;

#pragma unroll
        for (int s = 0; s < 4; ++s) {
#pragma unroll
            for (int jp = 0; jp < 4; ++jp) {
                uint32_t kh0, kh1, kh2, kh3, kl0, kl1, kl2, kl3;
                uint32_t ka = ka_row + (uint32_t)(jp * 16 * AT_ROWB) + (uint32_t)(s * 32 + (ltile >> 1) * 16);
                LDSM_X4(kh0, kh1, kh2, kh3, sKh + ka);
                LDSM_X4(kl0, kl1, kl2, kl3, sKl + ka);
                uint32_t be_h[2] = {kh0, kh2}, bo_h[2] = {kh1, kh3};
                uint32_t be_l[2] = {kl0, kl2}, bo_l[2] = {kl1, kl3};
                MMA_BF16(c[2 * jp],     qfh[s], be_h);
                MMA_BF16(c[2 * jp],     qfh[s], be_l);
                MMA_BF16(c[2 * jp],     qfl[s], be_h);
                MMA_BF16(c[2 * jp + 1], qfh[s], bo_h);
                MMA_BF16(c[2 * jp + 1], qfh[s], bo_l);
                MMA_BF16(c[2 * jp + 1], qfl[s], bo_h);
            }
        }

        // ---- mask + online softmax ----
        float rm0 = -1e30f, rm1 = -1e30f;
#pragma unroll
        for (int j = 0; j < 8; ++j) {
            int jj = kc * 64 + 8 * j + 2 * tig;
            bool ok;
            ok = (jj     <= i0) && (jj     + (WINDOW - 1) >= i0); c[j][0] = ok ? c[j][0] : -1e30f;
            ok = (jj + 1 <= i0) && (jj + 1 + (WINDOW - 1) >= i0); c[j][1] = ok ? c[j][1] : -1e30f;
            ok = (jj     <= i1) && (jj     + (WINDOW - 1) >= i1); c[j][2] = ok ? c[j][2] : -1e30f;
            ok = (jj + 1 <= i1) && (jj + 1 + (WINDOW - 1) >= i1); c[j][3] = ok ? c[j][3] : -1e30f;
            rm0 = fmaxf(rm0, fmaxf(c[j][0], c[j][1]));
            rm1 = fmaxf(rm1, fmaxf(c[j][2], c[j][3]));
        }
        rm0 = fmaxf(rm0, __shfl_xor_sync(0xffffffffu, rm0, 1));
        rm0 = fmaxf(rm0, __shfl_xor_sync(0xffffffffu, rm0, 2));
        rm1 = fmaxf(rm1, __shfl_xor_sync(0xffffffffu, rm1, 1));
        rm1 = fmaxf(rm1, __shfl_xor_sync(0xffffffffu, rm1, 2));
        float mn0 = fmaxf(m0, rm0), mn1 = fmaxf(m1, rm1);
        float cor0 = __expf(m0 - mn0), cor1 = __expf(m1 - mn1);
        float rs0 = 0.f, rs1 = 0.f;
#pragma unroll
        for (int j = 0; j < 8; ++j) {
            c[j][0] = (c[j][0] > -5e29f) ? __expf(c[j][0] - mn0) : 0.f;
            c[j][1] = (c[j][1] > -5e29f) ? __expf(c[j][1] - mn0) : 0.f;
            c[j][2] = (c[j][2] > -5e29f) ? __expf(c[j][2] - mn1) : 0.f;
            c[j][3] = (c[j][3] > -5e29f) ? __expf(c[j][3] - mn1) : 0.f;
            rs0 += c[j][0] + c[j][1];
            rs1 += c[j][2] + c[j][3];
        }
        rs0 += __shfl_xor_sync(0xffffffffu, rs0, 1);
        rs0 += __shfl_xor_sync(0xffffffffu, rs0, 2);
        rs1 += __shfl_xor_sync(0xffffffffu, rs1, 1);
        rs1 += __shfl_xor_sync(0xffffffffu, rs1, 2);
        l0 = l0 * cor0 + rs0; m0 = mn0;
        l1 = l1 * cor1 + rs1; m1 = mn1;
#pragma unroll
        for (int j = 0; j < 8; ++j) {
            o[j][0] *= cor0; o[j][1] *= cor0;
            o[j][2] *= cor1; o[j][3] *= cor1;
        }

        // ---- O += P V  (P from S frags: hi/lo split) ----
#pragma unroll
        for (int t = 0; t < 4; ++t) {
            uint32_t pfh[4], pfl[4];
#pragma unroll
            for (int u = 0; u < 4; ++u) {
                float p0 = c[2 * t + (u >> 1)][(u & 1) ? 2 : 0];
                float p1 = c[2 * t + (u >> 1)][(u & 1) ? 3 : 1];
                uint32_t wh = pack_bf16(p0, p1);
                float l0f = p0 - __uint_as_float(wh << 16);
                float l1f = p1 - __uint_as_float(wh & 0xFFFF0000u);
                pfh[u] = wh;
                pfl[u] = pack_bf16(l0f, l1f);
            }
            // reorder to a0..a3: a0=(row g,k lo)=u0? mapping below
            // u: (u>>1)=tile sel (2t / 2t+1 -> k low/high 8), (u&1)=row sel (g / g+8)
            uint32_t afh[4] = {pfh[0], pfh[1], pfh[2], pfh[3]};
            uint32_t afl[4] = {pfl[0], pfl[1], pfl[2], pfl[3]};
#pragma unroll
            for (int jdp = 0; jdp < 4; ++jdp) {
                uint32_t vh0, vh1, vh2, vh3, vl0, vl1, vl2, vl3;
                uint32_t va = va_row + (uint32_t)(t * 16 * AT_ROWB) + (uint32_t)(jdp * 32 + (ltile >> 1) * 16);
                LDSM_X4T(vh0, vh1, vh2, vh3, sVh + va);
                LDSM_X4T(vl0, vl1, vl2, vl3, sVl + va);
                uint32_t be_h[2] = {vh0, vh1}, bo_h[2] = {vh2, vh3};
                uint32_t be_l[2] = {vl0, vl1}, bo_l[2] = {vl2, vl3};
                MMA_BF16(o[2 * jdp],     afh, be_h);
                MMA_BF16(o[2 * jdp],     afh, be_l);
                MMA_BF16(o[2 * jdp],     afl, be_h);
                MMA_BF16(o[2 * jdp + 1], afh, bo_h);
                MMA_BF16(o[2 * jdp + 1], afh, bo_l);
                MMA_BF16(o[2 * jdp + 1], afl, bo_h);
            }
        }

        __syncthreads();
        if (ci + 2 < nch) { load_kv(lo + ci + 2, ci & 1); cp_commit(); }
    }

    // ---- epilogue: normalize, split, store token-major ----
    float inv0 = 1.f / l0, inv1 = 1.f / l1;
    const int t0 = q0 + warp * 16 + g;
#pragma unroll
    for (int jd = 0; jd < 8; ++jd) {
        int col = h * 64 + 8 * jd + 2 * tig;
        {
            float v0 = o[jd][0] * inv0, v1 = o[jd][1] * inv0;
            uint32_t wh = pack_bf16(v0, v1);
            float e0 = v0 - __uint_as_float(wh << 16);
            float e1 = v1 - __uint_as_float(wh & 0xFFFF0000u);
            uint32_t wl = pack_bf16(e0, e1);
            size_t idx = ((size_t)(b * T_SEQ + t0)) * DMODEL + col;
            *(uint32_t*)&ahi[idx] = wh;
            *(uint32_t*)&alo[idx] = wl;
        }
        {
            float v0 = o[jd][2] * inv1, v1 = o[jd][3] * inv1;
            uint32_t wh = pack_bf16(v0, v1);
            float e0 = v0 - __uint_as_float(wh << 16);
            float e1 = v1 - __uint_as_float(wh & 0xFFFF0000u);
            uint32_t wl = pack_bf16(e0, e1);
            size_t idx = ((size_t)(b * T_SEQ + t0 + 8)) * DMODEL + col;
            *(uint32_t*)&ahi[idx] = wh;
            *(uint32_t*)&alo[idx] = wl;
        }
    }
}

// ---------------------------------------------------------------------------
// Launch
// ---------------------------------------------------------------------------
extern "C" void kernel_launch(void* const* d_in, const int* in_sizes, int n_in,
                              void* d_out, int out_size) {
    const float* x     = (const float*)d_in[0];
    const float* cosb  = (const float*)d_in[1];
    const float* sinb  = (const float*)d_in[2];
    const float* qkv_w = (const float*)d_in[3];
    const float* out_w = (const float*)d_in[4];
    float* out = (float*)d_out;

    float *qkv = nullptr;
    bf16t *xhi, *xlo, *whi, *wlo, *ohi, *olo, *ahi, *alo;
    cudaGetSymbolAddress((void**)&qkv, g_qkv);
    cudaGetSymbolAddress((void**)&xhi, g_xhi);
    cudaGetSymbolAddress((void**)&xlo, g_xlo);
    cudaGetSymbolAddress((void**)&whi, g_whi);
    cudaGetSymbolAddress((void**)&wlo, g_wlo);
    cudaGetSymbolAddress((void**)&ohi, g_ohi);
    cudaGetSymbolAddress((void**)&olo, g_olo);
    cudaGetSymbolAddress((void**)&ahi, g_ahi);
    cudaGetSymbolAddress((void**)&alo, g_alo);

    cudaFuncSetAttribute(gemm_hmma_x3, cudaFuncAttributeMaxDynamicSharedMemorySize, GEMM_SMEM);
    cudaFuncSetAttribute(attn_hmma, cudaFuncAttributeMaxDynamicSharedMemorySize, ATTN_SMEM);

    // 0) Split inputs/weights into bf16 hi/lo
    split_kernel<<<(NTOK * DMODEL / 4 + 255) / 256, 256>>>(x, xhi, xlo, NTOK * DMODEL / 4);
    split_kernel<<<(QKV_F * DMODEL / 4 + 255) / 256, 256>>>(qkv_w, whi, wlo, QKV_F * DMODEL / 4);
    split_kernel<<<(DMODEL * DMODEL / 4 + 255) / 256, 256>>>(out_w, ohi, olo, DMODEL * DMODEL / 4);

    // 1) QKV projection (HMMA bf16x3)
    {
        dim3 grid(QKV_F / 128, NTOK / 128);
        gemm_hmma_x3<<<grid, 256, GEMM_SMEM>>>(xhi, xlo, whi, wlo, qkv, QKV_F);
    }
    // 2) RoPE + head-major bf16 hi/lo split
    rope_split_kernel<<<(NTOK * 512 + 255) / 256, 256>>>(qkv, cosb, sinb);
    // 3) Flash attention on HMMA (bf16x3), writes bf16 hi/lo token-major
    {
        dim3 grid(T_SEQ / 64, NHEADS, BATCH);
        attn_hmma<<<grid, 128, ATTN_SMEM>>>(ahi, alo);
    }
    // 4) Output projection (HMMA bf16x3)
    {
        dim3 grid(DMODEL / 128, NTOK / 128);
        gemm_hmma_x3<<<grid, 256, GEMM_SMEM>>>(ahi, alo, ohi, olo, out, DMODEL);
    }
}